// round 13
// baseline (speedup 1.0000x reference)
#include <cuda_runtime.h>
#include <cuda_bf16.h>
#include <math.h>

// ---------------- problem constants ----------------
#define Bn     32
#define Sn     2304
#define Dn     1280
#define Hn     16
#define HDn    96
#define HHD    1536      // Hn*HDn
#define Ln     64
#define INTERn 5120
#define DEPTHn 6
#define EPSf   1e-5f

// ---------------- scratch: __device__ globals (no cudaMalloc allowed) ----------------
__device__ float g_xhat[(size_t)Bn*Sn*Dn];      // normalized context (layer-independent)
__device__ float g_lat [(size_t)Bn*Ln*Dn];      // latent residual stream
__device__ float g_lhat[(size_t)Bn*Ln*Dn];      // LN(lat) for attention block
__device__ float g_mlph[(size_t)Bn*Ln*Dn];      // LN(lat) for MLP block
__device__ float g_Kc  [(size_t)Bn*Sn*HHD];     // context K (head-LN applied in place)
__device__ float g_Vc  [(size_t)Bn*Sn*HHD];     // context V
__device__ float g_Q   [(size_t)Bn*Ln*HHD];
__device__ float g_Kl  [(size_t)Bn*Ln*HHD];     // latent K
__device__ float g_Vl  [(size_t)Bn*Ln*HHD];     // latent V
__device__ float g_att [(size_t)Bn*Ln*HHD];     // attention output (heads merged)
__device__ float g_hid [(size_t)Bn*Ln*INTERn];  // MLP hidden

// ---------------- helpers ----------------
__device__ __forceinline__ unsigned f2tf(float x) {
    unsigned r;
    asm("cvt.rna.tf32.f32 %0, %1;" : "=r"(r) : "f"(x));
    return r;
}

__device__ __forceinline__ void mma_tf32(float* c, const unsigned* a, const unsigned* b) {
    asm volatile(
        "mma.sync.aligned.m16n8k8.row.col.f32.tf32.tf32.f32 "
        "{%0,%1,%2,%3}, {%4,%5,%6,%7}, {%8,%9}, {%0,%1,%2,%3};\n"
        : "+f"(c[0]), "+f"(c[1]), "+f"(c[2]), "+f"(c[3])
        : "r"(a[0]), "r"(a[1]), "r"(a[2]), "r"(a[3]), "r"(b[0]), "r"(b[1]));
}

// ---------------- row LayerNorm, width = 1280 ----------------
template<bool AFF>
__global__ __launch_bounds__(256) void ln_kernel(
    const float* __restrict__ in, float* __restrict__ out,
    const float* __restrict__ g, const float* __restrict__ b)
{
    __shared__ float row[Dn];
    __shared__ float red[8];
    __shared__ float stat[2];
    const int r = blockIdx.x, tid = threadIdx.x;
    const int lane = tid & 31, w = tid >> 5;
    const float* x = in + (size_t)r * Dn;

    float s = 0.f;
    for (int i = tid; i < Dn; i += 256) { float v = x[i]; row[i] = v; s += v; }
    #pragma unroll
    for (int o = 16; o; o >>= 1) s += __shfl_xor_sync(0xffffffffu, s, o);
    if (lane == 0) red[w] = s;
    __syncthreads();
    if (tid == 0) { float t = 0.f; for (int j = 0; j < 8; j++) t += red[j]; stat[0] = t * (1.f/Dn); }
    __syncthreads();
    const float mean = stat[0];

    float s2 = 0.f;
    for (int i = tid; i < Dn; i += 256) { float d = row[i] - mean; s2 += d * d; }
    #pragma unroll
    for (int o = 16; o; o >>= 1) s2 += __shfl_xor_sync(0xffffffffu, s2, o);
    if (lane == 0) red[w] = s2;
    __syncthreads();
    if (tid == 0) { float t = 0.f; for (int j = 0; j < 8; j++) t += red[j]; stat[1] = rsqrtf(t * (1.f/Dn) + EPSf); }
    __syncthreads();
    const float rstd = stat[1];

    float* o = out + (size_t)r * Dn;
    for (int i = tid; i < Dn; i += 256) {
        float v = (row[i] - mean) * rstd;
        o[i] = AFF ? (v * g[i] + b[i]) : v;
    }
}

// ---------------- broadcast latents to batch ----------------
__global__ void bcast_lat(const float* __restrict__ lat0, float* __restrict__ out) {
    int i = blockIdx.x * 256 + threadIdx.x;
    if (i < Bn * Ln * Dn) out[i] = lat0[i % (Ln * Dn)];
}

// ---------------- per-head LayerNorm over head_dim=96 (in place) ----------------
__global__ __launch_bounds__(512) void head_ln(
    float* __restrict__ x, const float* __restrict__ g, const float* __restrict__ b)
{
    const int row = blockIdx.x;
    const int w = threadIdx.x >> 5, lane = threadIdx.x & 31;
    float* p = x + (size_t)row * HHD + w * HDn;
    float a0 = p[lane], a1 = p[lane + 32], a2 = p[lane + 64];
    float s = a0 + a1 + a2;
    #pragma unroll
    for (int o = 16; o; o >>= 1) s += __shfl_xor_sync(0xffffffffu, s, o);
    const float mean = s * (1.f / HDn);
    float d0 = a0 - mean, d1 = a1 - mean, d2 = a2 - mean;
    float v = d0 * d0 + d1 * d1 + d2 * d2;
    #pragma unroll
    for (int o = 16; o; o >>= 1) v += __shfl_xor_sync(0xffffffffu, v, o);
    const float rstd = rsqrtf(v * (1.f / HDn) + EPSf);
    p[lane]      = d0 * rstd * g[lane]      + b[lane];
    p[lane + 32] = d1 * rstd * g[lane + 32] + b[lane + 32];
    p[lane + 64] = d2 * rstd * g[lane + 64] + b[lane + 64];
}

// ---------------- TF32 GEMM: C[M,N] = A[M,K] @ B[K,N] ----------------
// CTA tile 128x256, 8 warps in 2x4 grid, warp tile 64x64 (4x8 m16n8 frags).
// Double-buffered smem + register prefetch of the next k-tile.
// MODE_A: 0 plain, 1 per-column affine on A (a*g[k]+b[k]); EPI: 0 none, 1 relu, 2 +res
#define BM 128
#define BN 256
#define BK 32
#define PADA_K (BK + 4)    // 36: stride mod 32 = 4 -> frag bank 4*(lane>>2)+(lane&3)
#define PADB   (BN + 8)    // 264: stride mod 32 = 8 -> frag bank 8*(lane&3)+(lane>>2)
#define ASZ (BM * PADA_K)  // 4608 words per buffer
#define BSZ (BK * PADB)    // 8448 words per buffer
#define GEMM_SMEM ((2*ASZ + 2*BSZ) * 4 + 2 * 1280 * 4)   // 114688 bytes

template<int MODE_A, int EPI>
__global__ __launch_bounds__(256, 1) void gemm_tf32(
    const float* __restrict__ A, const float* __restrict__ B, float* __restrict__ C,
    int M, int N, int K,
    const float* __restrict__ ga, const float* __restrict__ ba,
    const float* __restrict__ res)
{
    extern __shared__ unsigned dynsm[];
    unsigned* As = dynsm;                 // [2][BM][PADA_K]
    unsigned* Bs = dynsm + 2 * ASZ;       // [2][BK][PADB]
    float* gsh = (float*)(dynsm + 2 * ASZ + 2 * BSZ);
    float* bsh = gsh + 1280;

    const int tid  = threadIdx.x;
    const int lane = tid & 31;
    const int warp = tid >> 5;
    const int warpM = (warp & 1) * 64;    // 2 warps along M
    const int warpN = (warp >> 1) * 64;   // 4 warps along N

    const int nTilesN = N / BN;
    const int bidn = blockIdx.x % nTilesN;
    const int bidm = blockIdx.x / nTilesN;

    const float* Ablk = A + (size_t)bidm * BM * K;
    const float* Bblk = B + (size_t)bidn * BN;

    // staging indices (constant per thread)
    // A: 4 x float4 : s = tid + it*256 ; row = s>>3, kcol = (s&7)*4
    // B: 8 x float4 : s = tid + it*256 ; krow = s>>6, ncol = (s&63)*4
    if (MODE_A) {
        for (int i = tid; i < K; i += 256) { gsh[i] = ga[i]; bsh[i] = ba[i]; }
        __syncthreads();
    }

    float4 pa[4];
    float4 pb[8];

    // ---- load k-tile k0 into registers ----
    auto load_tile = [&](int k0) {
        #pragma unroll
        for (int it = 0; it < 4; it++) {
            int s = tid + it * 256;
            pa[it] = *(const float4*)(Ablk + (size_t)(s >> 3) * K + k0 + (s & 7) * 4);
        }
        #pragma unroll
        for (int it = 0; it < 8; it++) {
            int s = tid + it * 256;
            pb[it] = *(const float4*)(Bblk + (size_t)(k0 + (s >> 6)) * N + (s & 63) * 4);
        }
    };
    // ---- convert + store registers into smem buffer p (tile k0 for gsh index) ----
    auto store_tile = [&](int p, int k0) {
        unsigned* Ab = As + p * ASZ;
        unsigned* Bb = Bs + p * BSZ;
        #pragma unroll
        for (int it = 0; it < 4; it++) {
            int s = tid + it * 256;
            int kq = (s & 7) * 4;
            float4 va = pa[it];
            if (MODE_A) {
                va.x = va.x * gsh[k0 + kq + 0] + bsh[k0 + kq + 0];
                va.y = va.y * gsh[k0 + kq + 1] + bsh[k0 + kq + 1];
                va.z = va.z * gsh[k0 + kq + 2] + bsh[k0 + kq + 2];
                va.w = va.w * gsh[k0 + kq + 3] + bsh[k0 + kq + 3];
            }
            uint4 ua;
            ua.x = f2tf(va.x); ua.y = f2tf(va.y); ua.z = f2tf(va.z); ua.w = f2tf(va.w);
            *(uint4*)&Ab[(s >> 3) * PADA_K + kq] = ua;
        }
        #pragma unroll
        for (int it = 0; it < 8; it++) {
            int s = tid + it * 256;
            float4 vb = pb[it];
            uint4 ub;
            ub.x = f2tf(vb.x); ub.y = f2tf(vb.y); ub.z = f2tf(vb.z); ub.w = f2tf(vb.w);
            *(uint4*)&Bb[(s >> 6) * PADB + (s & 63) * 4] = ub;
        }
    };

    float acc[4][8][4];
    #pragma unroll
    for (int i = 0; i < 4; i++)
        #pragma unroll
        for (int j = 0; j < 8; j++)
            #pragma unroll
            for (int q = 0; q < 4; q++) acc[i][j][q] = 0.f;

    // prologue: stage tile 0
    load_tile(0);
    store_tile(0, 0);

    const int nK = K / BK;
    for (int t = 0; t < nK; t++) {
        __syncthreads();
        const int p = t & 1;
        const bool more = (t + 1 < nK);
        if (more) load_tile((t + 1) * BK);   // LDG overlaps the MMA loop below

        const unsigned* Ab = As + p * ASZ;
        const unsigned* Bb = Bs + p * BSZ;
        #pragma unroll
        for (int ks = 0; ks < 4; ks++) {
            unsigned af[4][4];
            unsigned bf[8][2];
            const int c = ks * 8 + (lane & 3);
            const int rbase = warpM + (lane >> 2);
            #pragma unroll
            for (int mt = 0; mt < 4; mt++) {
                int r = rbase + mt * 16;
                af[mt][0] = Ab[r * PADA_K + c];
                af[mt][1] = Ab[(r + 8) * PADA_K + c];
                af[mt][2] = Ab[r * PADA_K + c + 4];
                af[mt][3] = Ab[(r + 8) * PADA_K + c + 4];
            }
            const int cbase = warpN + (lane >> 2);
            #pragma unroll
            for (int nt = 0; nt < 8; nt++) {
                int cc = cbase + nt * 8;
                bf[nt][0] = Bb[c * PADB + cc];
                bf[nt][1] = Bb[(c + 4) * PADB + cc];
            }
            #pragma unroll
            for (int mt = 0; mt < 4; mt++)
                #pragma unroll
                for (int nt = 0; nt < 8; nt++)
                    mma_tf32(acc[mt][nt], af[mt], bf[nt]);
        }

        if (more) store_tile(p ^ 1, (t + 1) * BK);  // fill other buffer; sync at loop top
    }

    // epilogue
    #pragma unroll
    for (int mt = 0; mt < 4; mt++) {
        int r = bidm * BM + warpM + mt * 16 + (lane >> 2);
        #pragma unroll
        for (int nt = 0; nt < 8; nt++) {
            int cc = bidn * BN + warpN + nt * 8 + 2 * (lane & 3);
            float v00 = acc[mt][nt][0], v01 = acc[mt][nt][1];
            float v10 = acc[mt][nt][2], v11 = acc[mt][nt][3];
            if (EPI == 1) {
                v00 = fmaxf(v00, 0.f); v01 = fmaxf(v01, 0.f);
                v10 = fmaxf(v10, 0.f); v11 = fmaxf(v11, 0.f);
            }
            if (EPI == 2) {
                v00 += res[(size_t)r * N + cc];
                v01 += res[(size_t)r * N + cc + 1];
                v10 += res[(size_t)(r + 8) * N + cc];
                v11 += res[(size_t)(r + 8) * N + cc + 1];
            }
            C[(size_t)r * N + cc]           = v00;
            C[(size_t)r * N + cc + 1]       = v01;
            C[(size_t)(r + 8) * N + cc]     = v10;
            C[(size_t)(r + 8) * N + cc + 1] = v11;
        }
    }
}

// ---------------- flash attention: one CTA per (b, h) ----------------
#define PQ 100   // stride mod 32 == 4 (row indexed by lane/4)
#define PK 100
#define PV 104   // stride mod 32 == 8 (row indexed by lane%4)
#define PP 68
#define ATTN_SMEM ((64*(PQ + PK + PV + PP)) * 4)

__global__ __launch_bounds__(128) void attn_kernel(
    const float* __restrict__ Qg, const float* __restrict__ Kc, const float* __restrict__ Kl,
    const float* __restrict__ Vc, const float* __restrict__ Vl, float* __restrict__ Og)
{
    extern __shared__ unsigned sm[];
    unsigned* Qs = sm;                 // [64][PQ]
    unsigned* Ks = Qs + 64 * PQ;       // [64][PK]
    unsigned* Vs = Ks + 64 * PK;       // [64][PV]
    unsigned* Ps = Vs + 64 * PV;       // [64][PP]

    const int b = blockIdx.x / Hn;
    const int h = blockIdx.x % Hn;
    const int tid = threadIdx.x;
    const int warp = tid >> 5, lane = tid & 31;
    const float scale = 0.10206207261596577f;  // 96^-0.5

    for (int s = tid; s < 64 * 24; s += 128) {
        int q = s / 24, dq = (s % 24) * 4;
        float4 v = *(const float4*)(Qg + ((size_t)(b * Ln + q) * HHD) + h * HDn + dq);
        Qs[q * PQ + dq + 0] = f2tf(v.x * scale);
        Qs[q * PQ + dq + 1] = f2tf(v.y * scale);
        Qs[q * PQ + dq + 2] = f2tf(v.z * scale);
        Qs[q * PQ + dq + 3] = f2tf(v.w * scale);
    }

    float o[12][4];
    #pragma unroll
    for (int i = 0; i < 12; i++) { o[i][0] = o[i][1] = o[i][2] = o[i][3] = 0.f; }
    float m0 = -1e30f, m1 = -1e30f, l0 = 0.f, l1 = 0.f;

    const int r0loc = warp * 16 + (lane >> 2);
    const int nTiles = (Sn + Ln) / 64;           // 37

    for (int t = 0; t < nTiles; t++) {
        __syncthreads();
        const int kbase = t * 64;
        for (int s = tid; s < 64 * 24; s += 128) {
            int ky = s / 24, dq = (s % 24) * 4;
            int gk = kbase + ky;
            const float* srck = (gk < Sn)
                ? (Kc + (size_t)(b * Sn + gk) * HHD + h * HDn + dq)
                : (Kl + (size_t)(b * Ln + gk - Sn) * HHD + h * HDn + dq);
            const float* srcv = (gk < Sn)
                ? (Vc + (size_t)(b * Sn + gk) * HHD + h * HDn + dq)
                : (Vl + (size_t)(b * Ln + gk - Sn) * HHD + h * HDn + dq);
            float4 vk = *(const float4*)srck;
            float4 vv = *(const float4*)srcv;
            Ks[ky * PK + dq + 0] = f2tf(vk.x);
            Ks[ky * PK + dq + 1] = f2tf(vk.y);
            Ks[ky * PK + dq + 2] = f2tf(vk.z);
            Ks[ky * PK + dq + 3] = f2tf(vk.w);
            Vs[ky * PV + dq + 0] = f2tf(vv.x);
            Vs[ky * PV + dq + 1] = f2tf(vv.y);
            Vs[ky * PV + dq + 2] = f2tf(vv.z);
            Vs[ky * PV + dq + 3] = f2tf(vv.w);
        }
        __syncthreads();

        float sf[8][4];
        #pragma unroll
        for (int nt = 0; nt < 8; nt++) { sf[nt][0] = sf[nt][1] = sf[nt][2] = sf[nt][3] = 0.f; }
        #pragma unroll
        for (int ks = 0; ks < 12; ks++) {
            const int c = ks * 8 + (lane & 3);
            unsigned a[4];
            a[0] = Qs[r0loc * PQ + c];
            a[1] = Qs[(r0loc + 8) * PQ + c];
            a[2] = Qs[r0loc * PQ + c + 4];
            a[3] = Qs[(r0loc + 8) * PQ + c + 4];
            #pragma unroll
            for (int nt = 0; nt < 8; nt++) {
                unsigned bb[2];
                int key = nt * 8 + (lane >> 2);
                bb[0] = Ks[key * PK + c];
                bb[1] = Ks[key * PK + c + 4];
                mma_tf32(sf[nt], a, bb);
            }
        }

        float mt0 = -1e30f, mt1 = -1e30f;
        #pragma unroll
        for (int nt = 0; nt < 8; nt++) {
            mt0 = fmaxf(mt0, fmaxf(sf[nt][0], sf[nt][1]));
            mt1 = fmaxf(mt1, fmaxf(sf[nt][2], sf[nt][3]));
        }
        mt0 = fmaxf(mt0, __shfl_xor_sync(0xffffffffu, mt0, 1));
        mt0 = fmaxf(mt0, __shfl_xor_sync(0xffffffffu, mt0, 2));
        mt1 = fmaxf(mt1, __shfl_xor_sync(0xffffffffu, mt1, 1));
        mt1 = fmaxf(mt1, __shfl_xor_sync(0xffffffffu, mt1, 2));
        const float mn0 = fmaxf(m0, mt0), mn1 = fmaxf(m1, mt1);
        const float al0 = __expf(m0 - mn0), al1 = __expf(m1 - mn1);
        m0 = mn0; m1 = mn1;

        float ps0 = 0.f, ps1 = 0.f;
        #pragma unroll
        for (int nt = 0; nt < 8; nt++) {
            int cc = nt * 8 + 2 * (lane & 3);
            float p00 = __expf(sf[nt][0] - mn0);
            float p01 = __expf(sf[nt][1] - mn0);
            float p10 = __expf(sf[nt][2] - mn1);
            float p11 = __expf(sf[nt][3] - mn1);
            ps0 += p00 + p01;
            ps1 += p10 + p11;
            Ps[r0loc * PP + cc]           = f2tf(p00);
            Ps[r0loc * PP + cc + 1]       = f2tf(p01);
            Ps[(r0loc + 8) * PP + cc]     = f2tf(p10);
            Ps[(r0loc + 8) * PP + cc + 1] = f2tf(p11);
        }
        ps0 += __shfl_xor_sync(0xffffffffu, ps0, 1);
        ps0 += __shfl_xor_sync(0xffffffffu, ps0, 2);
        ps1 += __shfl_xor_sync(0xffffffffu, ps1, 1);
        ps1 += __shfl_xor_sync(0xffffffffu, ps1, 2);
        l0 = l0 * al0 + ps0;
        l1 = l1 * al1 + ps1;

        #pragma unroll
        for (int i = 0; i < 12; i++) {
            o[i][0] *= al0; o[i][1] *= al0;
            o[i][2] *= al1; o[i][3] *= al1;
        }
        __syncwarp();

        #pragma unroll
        for (int ks = 0; ks < 8; ks++) {
            const int kk = ks * 8 + (lane & 3);
            unsigned a[4];
            a[0] = Ps[r0loc * PP + kk];
            a[1] = Ps[(r0loc + 8) * PP + kk];
            a[2] = Ps[r0loc * PP + kk + 4];
            a[3] = Ps[(r0loc + 8) * PP + kk + 4];
            #pragma unroll
            for (int nt = 0; nt < 12; nt++) {
                unsigned bb[2];
                int n = nt * 8 + (lane >> 2);
                bb[0] = Vs[kk * PV + n];
                bb[1] = Vs[(kk + 4) * PV + n];
                mma_tf32(o[nt], a, bb);
            }
        }
    }

    const float inv0 = 1.f / l0, inv1 = 1.f / l1;
    #pragma unroll
    for (int nt = 0; nt < 12; nt++) {
        int cc = nt * 8 + 2 * (lane & 3);
        size_t base0 = (size_t)(b * Ln + r0loc) * HHD + h * HDn + cc;
        size_t base1 = (size_t)(b * Ln + r0loc + 8) * HHD + h * HDn + cc;
        Og[base0]     = o[nt][0] * inv0;
        Og[base0 + 1] = o[nt][1] * inv0;
        Og[base1]     = o[nt][2] * inv1;
        Og[base1 + 1] = o[nt][3] * inv1;
    }
}

// ---------------- host orchestration ----------------
extern "C" void kernel_launch(void* const* d_in, const int* in_sizes, int n_in,
                              void* d_out, int out_size)
{
    const float* context = (const float*)d_in[0];
    const float* latents = (const float*)d_in[1];
    const float* ctx_g   = (const float*)d_in[2];
    const float* ctx_b   = (const float*)d_in[3];
    const float* lat_g   = (const float*)d_in[4];
    const float* lat_b   = (const float*)d_in[5];
    const float* q_g     = (const float*)d_in[6];
    const float* q_b     = (const float*)d_in[7];
    const float* k_g     = (const float*)d_in[8];
    const float* k_b     = (const float*)d_in[9];
    const float* Wq      = (const float*)d_in[10];
    const float* Wk      = (const float*)d_in[11];
    const float* Wv      = (const float*)d_in[12];
    const float* Wo      = (const float*)d_in[13];
    const float* mlp_g   = (const float*)d_in[14];
    const float* mlp_b   = (const float*)d_in[15];
    const float* Wfc     = (const float*)d_in[16];
    const float* Wcp     = (const float*)d_in[17];
    const float* f_g     = (const float*)d_in[18];
    const float* f_b     = (const float*)d_in[19];
    float* out = (float*)d_out;

    float *xhat, *lat, *lhat, *mlph, *Kc, *Vc, *Qb, *Kl, *Vl, *att, *hid;
    cudaGetSymbolAddress((void**)&xhat, g_xhat);
    cudaGetSymbolAddress((void**)&lat,  g_lat);
    cudaGetSymbolAddress((void**)&lhat, g_lhat);
    cudaGetSymbolAddress((void**)&mlph, g_mlph);
    cudaGetSymbolAddress((void**)&Kc,   g_Kc);
    cudaGetSymbolAddress((void**)&Vc,   g_Vc);
    cudaGetSymbolAddress((void**)&Qb,   g_Q);
    cudaGetSymbolAddress((void**)&Kl,   g_Kl);
    cudaGetSymbolAddress((void**)&Vl,   g_Vl);
    cudaGetSymbolAddress((void**)&att,  g_att);
    cudaGetSymbolAddress((void**)&hid,  g_hid);

    cudaFuncSetAttribute(attn_kernel, cudaFuncAttributeMaxDynamicSharedMemorySize, ATTN_SMEM);
    cudaFuncSetAttribute(gemm_tf32<1,0>, cudaFuncAttributeMaxDynamicSharedMemorySize, GEMM_SMEM);
    cudaFuncSetAttribute(gemm_tf32<0,0>, cudaFuncAttributeMaxDynamicSharedMemorySize, GEMM_SMEM);
    cudaFuncSetAttribute(gemm_tf32<0,1>, cudaFuncAttributeMaxDynamicSharedMemorySize, GEMM_SMEM);
    cudaFuncSetAttribute(gemm_tf32<0,2>, cudaFuncAttributeMaxDynamicSharedMemorySize, GEMM_SMEM);

    const int MBIG = Bn * Sn;   // 73728
    const int MLAT = Bn * Ln;   // 2048

    // context LN (once; per-layer gamma/beta folded into GEMM A-load)
    ln_kernel<false><<<MBIG, 256>>>(context, xhat, nullptr, nullptr);
    bcast_lat<<<(Bn * Ln * Dn + 255) / 256, 256>>>(latents, lat);

    for (int i = 0; i < DEPTHn; i++) {
        const float* Wqi  = Wq  + (size_t)i * Dn * HHD;
        const float* Wki  = Wk  + (size_t)i * Dn * HHD;
        const float* Wvi  = Wv  + (size_t)i * Dn * HHD;
        const float* Woi  = Wo  + (size_t)i * HHD * Dn;
        const float* Wfci = Wfc + (size_t)i * Dn * INTERn;
        const float* Wcpi = Wcp + (size_t)i * INTERn * Dn;

        ln_kernel<true><<<MLAT, 256>>>(lat, lhat, lat_g + i * Dn, lat_b + i * Dn);

        // context K/V projections (dominant cost)
        gemm_tf32<1,0><<<(MBIG/BM)*(HHD/BN), 256, GEMM_SMEM>>>(xhat, Wki, Kc, MBIG, HHD, Dn,
                                                    ctx_g + i * Dn, ctx_b + i * Dn, nullptr);
        gemm_tf32<1,0><<<(MBIG/BM)*(HHD/BN), 256, GEMM_SMEM>>>(xhat, Wvi, Vc, MBIG, HHD, Dn,
                                                    ctx_g + i * Dn, ctx_b + i * Dn, nullptr);
        // latent Q/K/V
        gemm_tf32<0,0><<<(MLAT/BM)*(HHD/BN), 256, GEMM_SMEM>>>(lhat, Wqi, Qb, MLAT, HHD, Dn,
                                                    nullptr, nullptr, nullptr);
        gemm_tf32<0,0><<<(MLAT/BM)*(HHD/BN), 256, GEMM_SMEM>>>(lhat, Wki, Kl, MLAT, HHD, Dn,
                                                    nullptr, nullptr, nullptr);
        gemm_tf32<0,0><<<(MLAT/BM)*(HHD/BN), 256, GEMM_SMEM>>>(lhat, Wvi, Vl, MLAT, HHD, Dn,
                                                    nullptr, nullptr, nullptr);
        // per-head QK layer norms
        head_ln<<<MLAT, 512>>>(Qb, q_g + i * HDn, q_b + i * HDn);
        head_ln<<<MBIG, 512>>>(Kc, k_g + i * HDn, k_b + i * HDn);
        head_ln<<<MLAT, 512>>>(Kl, k_g + i * HDn, k_b + i * HDn);

        attn_kernel<<<Bn * Hn, 128, ATTN_SMEM>>>(Qb, Kc, Kl, Vc, Vl, att);

        // output projection + residual
        gemm_tf32<0,2><<<(MLAT/BM)*(Dn/BN), 256, GEMM_SMEM>>>(att, Woi, lat, MLAT, Dn, HHD,
                                                   nullptr, nullptr, lat);
        // MLP
        ln_kernel<true><<<MLAT, 256>>>(lat, mlph, mlp_g + i * Dn, mlp_b + i * Dn);
        gemm_tf32<0,1><<<(MLAT/BM)*(INTERn/BN), 256, GEMM_SMEM>>>(mlph, Wfci, hid, MLAT, INTERn, Dn,
                                                       nullptr, nullptr, nullptr);
        gemm_tf32<0,2><<<(MLAT/BM)*(Dn/BN), 256, GEMM_SMEM>>>(hid, Wcpi, lat, MLAT, Dn, INTERn,
                                                   nullptr, nullptr, lat);
    }

    ln_kernel<true><<<MLAT, 256>>>(lat, out, f_g, f_b);
}

// round 15
// speedup vs baseline: 1.0879x; 1.0879x over previous
#include <cuda_runtime.h>
#include <cuda_bf16.h>
#include <math.h>

// ---------------- problem constants ----------------
#define Bn     32
#define Sn     2304
#define Dn     1280
#define Hn     16
#define HDn    96
#define HHD    1536      // Hn*HDn
#define Ln     64
#define INTERn 5120
#define DEPTHn 6
#define EPSf   1e-5f

// ---------------- scratch: __device__ globals (no cudaMalloc allowed) ----------------
__device__ float g_xhat[(size_t)Bn*Sn*Dn];        // normalized context (layer-independent)
__device__ float g_lat [(size_t)Bn*Ln*Dn];        // latent residual stream
__device__ float g_lhat[(size_t)Bn*Ln*Dn];
__device__ float g_mlph[(size_t)Bn*Ln*Dn];
__device__ float g_Kc  [2][(size_t)Bn*Sn*HHD];    // context K, double-buffered by layer parity
__device__ float g_Vc  [2][(size_t)Bn*Sn*HHD];    // context V, double-buffered
__device__ float g_Q   [(size_t)Bn*Ln*HHD];
__device__ float g_Kl  [(size_t)Bn*Ln*HHD];
__device__ float g_Vl  [(size_t)Bn*Ln*HHD];
__device__ float g_att [(size_t)Bn*Ln*HHD];
__device__ float g_hid [(size_t)Bn*Ln*INTERn];

// ---------------- helpers ----------------
__device__ __forceinline__ unsigned f2tf(float x) {
    unsigned r;
    asm("cvt.rna.tf32.f32 %0, %1;" : "=r"(r) : "f"(x));
    return r;
}

__device__ __forceinline__ void mma_tf32(float* c, const unsigned* a, const unsigned* b) {
    asm volatile(
        "mma.sync.aligned.m16n8k8.row.col.f32.tf32.tf32.f32 "
        "{%0,%1,%2,%3}, {%4,%5,%6,%7}, {%8,%9}, {%0,%1,%2,%3};\n"
        : "+f"(c[0]), "+f"(c[1]), "+f"(c[2]), "+f"(c[3])
        : "r"(a[0]), "r"(a[1]), "r"(a[2]), "r"(a[3]), "r"(b[0]), "r"(b[1]));
}

// ---------------- row LayerNorm, width = 1280 ----------------
template<bool AFF>
__global__ __launch_bounds__(256) void ln_kernel(
    const float* __restrict__ in, float* __restrict__ out,
    const float* __restrict__ g, const float* __restrict__ b)
{
    __shared__ float row[Dn];
    __shared__ float red[8];
    __shared__ float stat[2];
    const int r = blockIdx.x, tid = threadIdx.x;
    const int lane = tid & 31, w = tid >> 5;
    const float* x = in + (size_t)r * Dn;

    float s = 0.f;
    for (int i = tid; i < Dn; i += 256) { float v = x[i]; row[i] = v; s += v; }
    #pragma unroll
    for (int o = 16; o; o >>= 1) s += __shfl_xor_sync(0xffffffffu, s, o);
    if (lane == 0) red[w] = s;
    __syncthreads();
    if (tid == 0) { float t = 0.f; for (int j = 0; j < 8; j++) t += red[j]; stat[0] = t * (1.f/Dn); }
    __syncthreads();
    const float mean = stat[0];

    float s2 = 0.f;
    for (int i = tid; i < Dn; i += 256) { float d = row[i] - mean; s2 += d * d; }
    #pragma unroll
    for (int o = 16; o; o >>= 1) s2 += __shfl_xor_sync(0xffffffffu, s2, o);
    if (lane == 0) red[w] = s2;
    __syncthreads();
    if (tid == 0) { float t = 0.f; for (int j = 0; j < 8; j++) t += red[j]; stat[1] = rsqrtf(t * (1.f/Dn) + EPSf); }
    __syncthreads();
    const float rstd = stat[1];

    float* o = out + (size_t)r * Dn;
    for (int i = tid; i < Dn; i += 256) {
        float v = (row[i] - mean) * rstd;
        o[i] = AFF ? (v * g[i] + b[i]) : v;
    }
}

// ---------------- broadcast latents to batch ----------------
__global__ void bcast_lat(const float* __restrict__ lat0, float* __restrict__ out) {
    int i = blockIdx.x * 256 + threadIdx.x;
    if (i < Bn * Ln * Dn) out[i] = lat0[i % (Ln * Dn)];
}

// ---------------- TF32 GEMM body (R12-proven): C[M,N] = A[M,K] @ B[K,N] ----------------
// MODE_A: 0 plain, 1 per-column affine on A (a*g[k]+b[k]); EPI: 0 none, 1 relu, 2 +res
#define BM 128
#define BN 128
#define BK 32
#define PADA_K (BK + 4)   // 36: frag bank 4*(lane>>2)+(lane&3), conflict-free; STS.128 staging conflict-free
#define PADB (BN + 8)     // 136: frag bank 8*(lane&3)+(lane>>2), conflict-free

template<int MODE_A, int EPI>
__device__ __forceinline__ void gemm_body(
    const float* __restrict__ A, const float* __restrict__ B, float* __restrict__ C,
    int M, int N, int K,
    const float* __restrict__ ga, const float* __restrict__ ba,
    const float* __restrict__ res)
{
    __shared__ unsigned As[BM][PADA_K];
    __shared__ unsigned Bs[BK][PADB];
    __shared__ float gsh[MODE_A ? 1280 : 1];
    __shared__ float bsh[MODE_A ? 1280 : 1];

    const int tid  = threadIdx.x;
    const int lane = tid & 31;
    const int warp = tid >> 5;
    const int warpM = (warp >> 2) * 64;
    const int warpN = (warp & 3) * 32;

    const int nTilesN = N / BN;
    const int bidn = blockIdx.x % nTilesN;
    const int bidm = blockIdx.x / nTilesN;

    const float* Ablk = A + (size_t)bidm * BM * K;
    const float* Bblk = B + (size_t)bidn * BN;

    if (MODE_A) {
        for (int i = tid; i < K; i += 256) { gsh[i] = ga[i]; bsh[i] = ba[i]; }
    }

    float acc[4][4][4];
    #pragma unroll
    for (int i = 0; i < 4; i++)
        #pragma unroll
        for (int j = 0; j < 4; j++)
            #pragma unroll
            for (int q = 0; q < 4; q++) acc[i][j][q] = 0.f;

    if (MODE_A) __syncthreads();

    for (int k0 = 0; k0 < K; k0 += BK) {
        __syncthreads();
        #pragma unroll
        for (int it = 0; it < 4; it++) {
            int s = tid + it * 256;
            int rrow = s >> 3;
            int kq = (s & 7) * 4;
            float4 va = *(const float4*)(Ablk + (size_t)rrow * K + k0 + kq);
            if (MODE_A) {
                va.x = va.x * gsh[k0 + kq + 0] + bsh[k0 + kq + 0];
                va.y = va.y * gsh[k0 + kq + 1] + bsh[k0 + kq + 1];
                va.z = va.z * gsh[k0 + kq + 2] + bsh[k0 + kq + 2];
                va.w = va.w * gsh[k0 + kq + 3] + bsh[k0 + kq + 3];
            }
            uint4 ua;
            ua.x = f2tf(va.x); ua.y = f2tf(va.y); ua.z = f2tf(va.z); ua.w = f2tf(va.w);
            *(uint4*)&As[rrow][kq] = ua;
        }
        #pragma unroll
        for (int it = 0; it < 4; it++) {
            int s = tid + it * 256;
            int kr = s >> 5;
            int nq = (s & 31) * 4;
            float4 vb = *(const float4*)(Bblk + (size_t)(k0 + kr) * N + nq);
            uint4 ub;
            ub.x = f2tf(vb.x); ub.y = f2tf(vb.y); ub.z = f2tf(vb.z); ub.w = f2tf(vb.w);
            *(uint4*)&Bs[kr][nq] = ub;
        }
        __syncthreads();

        #pragma unroll
        for (int ks = 0; ks < 4; ks++) {
            unsigned af[4][4];
            unsigned bf[4][2];
            const int c = ks * 8 + (lane & 3);
            const int rbase = warpM + (lane >> 2);
            #pragma unroll
            for (int mt = 0; mt < 4; mt++) {
                int r = rbase + mt * 16;
                af[mt][0] = As[r][c];
                af[mt][1] = As[r + 8][c];
                af[mt][2] = As[r][c + 4];
                af[mt][3] = As[r + 8][c + 4];
            }
            const int cbase = warpN + (lane >> 2);
            #pragma unroll
            for (int nt = 0; nt < 4; nt++) {
                int cc = cbase + nt * 8;
                bf[nt][0] = Bs[c][cc];
                bf[nt][1] = Bs[c + 4][cc];
            }
            #pragma unroll
            for (int mt = 0; mt < 4; mt++)
                #pragma unroll
                for (int nt = 0; nt < 4; nt++)
                    mma_tf32(acc[mt][nt], af[mt], bf[nt]);
        }
    }

    #pragma unroll
    for (int mt = 0; mt < 4; mt++) {
        int r = bidm * BM + warpM + mt * 16 + (lane >> 2);
        #pragma unroll
        for (int nt = 0; nt < 4; nt++) {
            int cc = bidn * BN + warpN + nt * 8 + 2 * (lane & 3);
            float v00 = acc[mt][nt][0], v01 = acc[mt][nt][1];
            float v10 = acc[mt][nt][2], v11 = acc[mt][nt][3];
            if (EPI == 1) {
                v00 = fmaxf(v00, 0.f); v01 = fmaxf(v01, 0.f);
                v10 = fmaxf(v10, 0.f); v11 = fmaxf(v11, 0.f);
            }
            if (EPI == 2) {
                v00 += res[(size_t)r * N + cc];
                v01 += res[(size_t)r * N + cc + 1];
                v10 += res[(size_t)(r + 8) * N + cc];
                v11 += res[(size_t)(r + 8) * N + cc + 1];
            }
            C[(size_t)r * N + cc]           = v00;
            C[(size_t)r * N + cc + 1]       = v01;
            C[(size_t)(r + 8) * N + cc]     = v10;
            C[(size_t)(r + 8) * N + cc + 1] = v11;
        }
    }
}

template<int MODE_A, int EPI>
__global__ __launch_bounds__(256) void gemm_tf32(
    const float* __restrict__ A, const float* __restrict__ B, float* __restrict__ C,
    int M, int N, int K,
    const float* __restrict__ ga, const float* __restrict__ ba,
    const float* __restrict__ res)
{
    gemm_body<MODE_A, EPI>(A, B, C, M, N, K, ga, ba, res);
}

// batched latent QKV: blockIdx.z selects (W, C) pair
__global__ __launch_bounds__(256) void gemm_qkv(
    const float* __restrict__ A,
    const float* __restrict__ W0, const float* __restrict__ W1, const float* __restrict__ W2,
    float* __restrict__ C0, float* __restrict__ C1, float* __restrict__ C2,
    int M, int N, int K)
{
    const float* B = (blockIdx.z == 0) ? W0 : (blockIdx.z == 1) ? W1 : W2;
    float* C       = (blockIdx.z == 0) ? C0 : (blockIdx.z == 1) ? C1 : C2;
    gemm_body<0, 0>(A, B, C, M, N, K, nullptr, nullptr, nullptr);
}

// ---------------- flash attention with folded Q/K head-LayerNorm ----------------
// One CTA per (b, h). Q[64,96] resident; 37 key tiles of 64 over concat(context, latents).
// Q and K are head-LayerNormed on the fly (2 threads per row, 48 elems each).
#define PQ 100   // stride mod 32 == 4
#define PK 100
#define PV 108   // stride mod 32 == 12: staging STS.128 and frag loads both conflict-free
#define PP 68
#define ATTN_SMEM ((64*(PQ + PK + PV + PP) + 192) * 4)

__global__ __launch_bounds__(128) void attn_kernel(
    const float* __restrict__ Qg, const float* __restrict__ Kc, const float* __restrict__ Kl,
    const float* __restrict__ Vc, const float* __restrict__ Vl, float* __restrict__ Og,
    const float* __restrict__ qg, const float* __restrict__ qb,
    const float* __restrict__ kg, const float* __restrict__ kb)
{
    extern __shared__ unsigned sm[];
    unsigned* Qs = sm;                 // [64][PQ]
    unsigned* Ks = Qs + 64 * PQ;       // [64][PK]
    unsigned* Vs = Ks + 64 * PK;       // [64][PV]
    unsigned* Ps = Vs + 64 * PV;       // [64][PP]
    float* ksg = (float*)(Ps + 64 * PP);   // [96]
    float* ksb = ksg + 96;                 // [96]

    const int b = blockIdx.x / Hn;
    const int h = blockIdx.x % Hn;
    const int tid = threadIdx.x;
    const int warp = tid >> 5, lane = tid & 31;
    const float scale = 0.10206207261596577f;  // 96^-0.5
    const int row = tid >> 1;          // 0..63
    const int off48 = (tid & 1) * 48;  // element offset of this thread's half-row

    if (tid < 96) { ksg[tid] = kg[tid]; ksb[tid] = kb[tid]; }

    // ---- Q: load, head-LN (pair reduction), scale, tf32 ----
    {
        const float* src = Qg + (size_t)(b * Ln + row) * HHD + h * HDn + off48;
        float4 qv[12];
        float s = 0.f;
        #pragma unroll
        for (int j = 0; j < 12; j++) {
            qv[j] = *(const float4*)(src + j * 4);
            s += qv[j].x + qv[j].y + qv[j].z + qv[j].w;
        }
        s += __shfl_xor_sync(0xffffffffu, s, 1);
        const float mean = s * (1.f / HDn);
        float v2 = 0.f;
        #pragma unroll
        for (int j = 0; j < 12; j++) {
            float d0 = qv[j].x - mean, d1 = qv[j].y - mean;
            float d2 = qv[j].z - mean, d3 = qv[j].w - mean;
            v2 += d0 * d0 + d1 * d1 + d2 * d2 + d3 * d3;
        }
        v2 += __shfl_xor_sync(0xffffffffu, v2, 1);
        const float rstd = rsqrtf(v2 * (1.f / HDn) + EPSf);
        #pragma unroll
        for (int j = 0; j < 12; j++) {
            const int e = off48 + j * 4;
            uint4 u;
            u.x = f2tf(((qv[j].x - mean) * rstd * qg[e + 0] + qb[e + 0]) * scale);
            u.y = f2tf(((qv[j].y - mean) * rstd * qg[e + 1] + qb[e + 1]) * scale);
            u.z = f2tf(((qv[j].z - mean) * rstd * qg[e + 2] + qb[e + 2]) * scale);
            u.w = f2tf(((qv[j].w - mean) * rstd * qg[e + 3] + qb[e + 3]) * scale);
            *(uint4*)&Qs[row * PQ + e] = u;
        }
    }

    float o[12][4];
    #pragma unroll
    for (int i = 0; i < 12; i++) { o[i][0] = o[i][1] = o[i][2] = o[i][3] = 0.f; }
    float m0 = -1e30f, m1 = -1e30f, l0 = 0.f, l1 = 0.f;

    const int r0loc = warp * 16 + (lane >> 2);
    const int nTiles = (Sn + Ln) / 64;   // 37

    for (int t = 0; t < nTiles; t++) {
        __syncthreads();   // protects K/V smem reuse; first iter also fences ksg/Qs
        const int gk = t * 64 + row;

        // ---- K: load + head-LN + tf32 ----
        {
            const float* srck = (gk < Sn)
                ? (Kc + (size_t)(b * Sn + gk) * HHD + h * HDn + off48)
                : (Kl + (size_t)(b * Ln + gk - Sn) * HHD + h * HDn + off48);
            float4 kv[12];
            float s = 0.f;
            #pragma unroll
            for (int j = 0; j < 12; j++) {
                kv[j] = *(const float4*)(srck + j * 4);
                s += kv[j].x + kv[j].y + kv[j].z + kv[j].w;
            }
            s += __shfl_xor_sync(0xffffffffu, s, 1);
            const float mean = s * (1.f / HDn);
            float v2 = 0.f;
            #pragma unroll
            for (int j = 0; j < 12; j++) {
                float d0 = kv[j].x - mean, d1 = kv[j].y - mean;
                float d2 = kv[j].z - mean, d3 = kv[j].w - mean;
                v2 += d0 * d0 + d1 * d1 + d2 * d2 + d3 * d3;
            }
            v2 += __shfl_xor_sync(0xffffffffu, v2, 1);
            const float rstd = rsqrtf(v2 * (1.f / HDn) + EPSf);
            #pragma unroll
            for (int j = 0; j < 12; j++) {
                const int e = off48 + j * 4;
                uint4 u;
                u.x = f2tf((kv[j].x - mean) * rstd * ksg[e + 0] + ksb[e + 0]);
                u.y = f2tf((kv[j].y - mean) * rstd * ksg[e + 1] + ksb[e + 1]);
                u.z = f2tf((kv[j].z - mean) * rstd * ksg[e + 2] + ksb[e + 2]);
                u.w = f2tf((kv[j].w - mean) * rstd * ksg[e + 3] + ksb[e + 3]);
                *(uint4*)&Ks[row * PK + e] = u;
            }
        }
        // ---- V: plain load + tf32 ----
        {
            const float* srcv = (gk < Sn)
                ? (Vc + (size_t)(b * Sn + gk) * HHD + h * HDn + off48)
                : (Vl + (size_t)(b * Ln + gk - Sn) * HHD + h * HDn + off48);
            #pragma unroll
            for (int j = 0; j < 12; j++) {
                float4 vv = *(const float4*)(srcv + j * 4);
                uint4 u;
                u.x = f2tf(vv.x); u.y = f2tf(vv.y); u.z = f2tf(vv.z); u.w = f2tf(vv.w);
                *(uint4*)&Vs[row * PV + off48 + j * 4] = u;
            }
        }
        __syncthreads();

        // S = Q @ K^T
        float sf[8][4];
        #pragma unroll
        for (int nt = 0; nt < 8; nt++) { sf[nt][0] = sf[nt][1] = sf[nt][2] = sf[nt][3] = 0.f; }
        #pragma unroll
        for (int ks = 0; ks < 12; ks++) {
            const int c = ks * 8 + (lane & 3);
            unsigned a[4];
            a[0] = Qs[r0loc * PQ + c];
            a[1] = Qs[(r0loc + 8) * PQ + c];
            a[2] = Qs[r0loc * PQ + c + 4];
            a[3] = Qs[(r0loc + 8) * PQ + c + 4];
            #pragma unroll
            for (int nt = 0; nt < 8; nt++) {
                unsigned bb[2];
                int key = nt * 8 + (lane >> 2);
                bb[0] = Ks[key * PK + c];
                bb[1] = Ks[key * PK + c + 4];
                mma_tf32(sf[nt], a, bb);
            }
        }

        // online softmax
        float mt0 = -1e30f, mt1 = -1e30f;
        #pragma unroll
        for (int nt = 0; nt < 8; nt++) {
            mt0 = fmaxf(mt0, fmaxf(sf[nt][0], sf[nt][1]));
            mt1 = fmaxf(mt1, fmaxf(sf[nt][2], sf[nt][3]));
        }
        mt0 = fmaxf(mt0, __shfl_xor_sync(0xffffffffu, mt0, 1));
        mt0 = fmaxf(mt0, __shfl_xor_sync(0xffffffffu, mt0, 2));
        mt1 = fmaxf(mt1, __shfl_xor_sync(0xffffffffu, mt1, 1));
        mt1 = fmaxf(mt1, __shfl_xor_sync(0xffffffffu, mt1, 2));
        const float mn0 = fmaxf(m0, mt0), mn1 = fmaxf(m1, mt1);
        const float al0 = __expf(m0 - mn0), al1 = __expf(m1 - mn1);
        m0 = mn0; m1 = mn1;

        float ps0 = 0.f, ps1 = 0.f;
        #pragma unroll
        for (int nt = 0; nt < 8; nt++) {
            int cc = nt * 8 + 2 * (lane & 3);
            float p00 = __expf(sf[nt][0] - mn0);
            float p01 = __expf(sf[nt][1] - mn0);
            float p10 = __expf(sf[nt][2] - mn1);
            float p11 = __expf(sf[nt][3] - mn1);
            ps0 += p00 + p01;
            ps1 += p10 + p11;
            Ps[r0loc * PP + cc]           = f2tf(p00);
            Ps[r0loc * PP + cc + 1]       = f2tf(p01);
            Ps[(r0loc + 8) * PP + cc]     = f2tf(p10);
            Ps[(r0loc + 8) * PP + cc + 1] = f2tf(p11);
        }
        ps0 += __shfl_xor_sync(0xffffffffu, ps0, 1);
        ps0 += __shfl_xor_sync(0xffffffffu, ps0, 2);
        ps1 += __shfl_xor_sync(0xffffffffu, ps1, 1);
        ps1 += __shfl_xor_sync(0xffffffffu, ps1, 2);
        l0 = l0 * al0 + ps0;
        l1 = l1 * al1 + ps1;

        #pragma unroll
        for (int i = 0; i < 12; i++) {
            o[i][0] *= al0; o[i][1] *= al0;
            o[i][2] *= al1; o[i][3] *= al1;
        }
        __syncwarp();

        // O += P @ V
        #pragma unroll
        for (int ks = 0; ks < 8; ks++) {
            const int kk = ks * 8 + (lane & 3);
            unsigned a[4];
            a[0] = Ps[r0loc * PP + kk];
            a[1] = Ps[(r0loc + 8) * PP + kk];
            a[2] = Ps[r0loc * PP + kk + 4];
            a[3] = Ps[(r0loc + 8) * PP + kk + 4];
            #pragma unroll
            for (int nt = 0; nt < 12; nt++) {
                unsigned bb[2];
                int n = nt * 8 + (lane >> 2);
                bb[0] = Vs[kk * PV + n];
                bb[1] = Vs[(kk + 4) * PV + n];
                mma_tf32(o[nt], a, bb);
            }
        }
    }

    const float inv0 = 1.f / l0, inv1 = 1.f / l1;
    #pragma unroll
    for (int nt = 0; nt < 12; nt++) {
        int cc = nt * 8 + 2 * (lane & 3);
        size_t base0 = (size_t)(b * Ln + r0loc) * HHD + h * HDn + cc;
        size_t base1 = (size_t)(b * Ln + r0loc + 8) * HHD + h * HDn + cc;
        Og[base0]     = o[nt][0] * inv0;
        Og[base0 + 1] = o[nt][1] * inv0;
        Og[base1]     = o[nt][2] * inv1;
        Og[base1 + 1] = o[nt][3] * inv1;
    }
}

// ---------------- host orchestration ----------------
extern "C" void kernel_launch(void* const* d_in, const int* in_sizes, int n_in,
                              void* d_out, int out_size)
{
    const float* context = (const float*)d_in[0];
    const float* latents = (const float*)d_in[1];
    const float* ctx_g   = (const float*)d_in[2];
    const float* ctx_b   = (const float*)d_in[3];
    const float* lat_g   = (const float*)d_in[4];
    const float* lat_b   = (const float*)d_in[5];
    const float* q_g     = (const float*)d_in[6];
    const float* q_b     = (const float*)d_in[7];
    const float* k_g     = (const float*)d_in[8];
    const float* k_b     = (const float*)d_in[9];
    const float* Wq      = (const float*)d_in[10];
    const float* Wk      = (const float*)d_in[11];
    const float* Wv      = (const float*)d_in[12];
    const float* Wo      = (const float*)d_in[13];
    const float* mlp_g   = (const float*)d_in[14];
    const float* mlp_b   = (const float*)d_in[15];
    const float* Wfc     = (const float*)d_in[16];
    const float* Wcp     = (const float*)d_in[17];
    const float* f_g     = (const float*)d_in[18];
    const float* f_b     = (const float*)d_in[19];
    float* out = (float*)d_out;

    float *xhat, *lat, *lhat, *mlph, *Kc0, *Vc0, *Qb, *Kl, *Vl, *att, *hid;
    cudaGetSymbolAddress((void**)&xhat, g_xhat);
    cudaGetSymbolAddress((void**)&lat,  g_lat);
    cudaGetSymbolAddress((void**)&lhat, g_lhat);
    cudaGetSymbolAddress((void**)&mlph, g_mlph);
    cudaGetSymbolAddress((void**)&Kc0,  g_Kc);
    cudaGetSymbolAddress((void**)&Vc0,  g_Vc);
    cudaGetSymbolAddress((void**)&Qb,   g_Q);
    cudaGetSymbolAddress((void**)&Kl,   g_Kl);
    cudaGetSymbolAddress((void**)&Vl,   g_Vl);
    cudaGetSymbolAddress((void**)&att,  g_att);
    cudaGetSymbolAddress((void**)&hid,  g_hid);
    const size_t KV_STRIDE = (size_t)Bn * Sn * HHD;

    cudaFuncSetAttribute(attn_kernel, cudaFuncAttributeMaxDynamicSharedMemorySize, ATTN_SMEM);

    // one-time stream/event setup (host resources, not device memory)
    static cudaStream_t s1 = nullptr;
    static cudaEvent_t ev0, evLat, evKV[DEPTHn], evAttn[DEPTHn];
    if (s1 == nullptr) {
        cudaStreamCreateWithFlags(&s1, cudaStreamNonBlocking);
        cudaEventCreateWithFlags(&ev0, cudaEventDisableTiming);
        cudaEventCreateWithFlags(&evLat, cudaEventDisableTiming);
        for (int i = 0; i < DEPTHn; i++) {
            cudaEventCreateWithFlags(&evKV[i], cudaEventDisableTiming);
            cudaEventCreateWithFlags(&evAttn[i], cudaEventDisableTiming);
        }
    }

    const int MBIG = Bn * Sn;   // 73728
    const int MLAT = Bn * Ln;   // 2048
    const int gridBig = (MBIG / BM) * (HHD / BN);       // 6912
    const int gridQKV = (MLAT / BM) * (HHD / BN);       // 192 (x3 in z)
    const int gridWo  = (MLAT / BM) * (Dn / BN);        // 160
    const int gridFc  = (MLAT / BM) * (INTERn / BN);    // 640

    // stream0: context LN (once), latent broadcast
    ln_kernel<false><<<MBIG, 256>>>(context, xhat, nullptr, nullptr);
    bcast_lat<<<(Bn * Ln * Dn + 255) / 256, 256>>>(latents, lat);
    cudaEventRecord(ev0, 0);
    cudaStreamWaitEvent(s1, ev0, 0);

    for (int i = 0; i < DEPTHn; i++) {
        const int p = i & 1;
        float* Kc = Kc0 + p * KV_STRIDE;
        float* Vc = Vc0 + p * KV_STRIDE;
        const float* Wqi  = Wq  + (size_t)i * Dn * HHD;
        const float* Wki  = Wk  + (size_t)i * Dn * HHD;
        const float* Wvi  = Wv  + (size_t)i * Dn * HHD;
        const float* Woi  = Wo  + (size_t)i * HHD * Dn;
        const float* Wfci = Wfc + (size_t)i * Dn * INTERn;
        const float* Wcpi = Wcp + (size_t)i * INTERn * Dn;

        // ---- stream0: big context K/V GEMMs (buffer parity p; reuse guarded) ----
        if (i >= 2) cudaStreamWaitEvent(0, evAttn[i - 2], 0);
        gemm_tf32<1,0><<<gridBig, 256>>>(xhat, Wki, Kc, MBIG, HHD, Dn,
                                         ctx_g + i * Dn, ctx_b + i * Dn, nullptr);
        gemm_tf32<1,0><<<gridBig, 256>>>(xhat, Wvi, Vc, MBIG, HHD, Dn,
                                         ctx_g + i * Dn, ctx_b + i * Dn, nullptr);
        cudaEventRecord(evKV[i], 0);

        // ---- stream1: latent chain ----
        ln_kernel<true><<<MLAT, 256, 0, s1>>>(lat, lhat, lat_g + i * Dn, lat_b + i * Dn);
        gemm_qkv<<<dim3(gridQKV, 1, 3), 256, 0, s1>>>(lhat, Wqi, Wki, Wvi,
                                                      Qb, Kl, Vl, MLAT, HHD, Dn);
        cudaStreamWaitEvent(s1, evKV[i], 0);
        attn_kernel<<<Bn * Hn, 128, ATTN_SMEM, s1>>>(Qb, Kc, Kl, Vc, Vl, att,
                                                     q_g + i * HDn, q_b + i * HDn,
                                                     k_g + i * HDn, k_b + i * HDn);
        cudaEventRecord(evAttn[i], s1);
        gemm_tf32<0,2><<<gridWo, 256, 0, s1>>>(att, Woi, lat, MLAT, Dn, HHD,
                                               nullptr, nullptr, lat);
        ln_kernel<true><<<MLAT, 256, 0, s1>>>(lat, mlph, mlp_g + i * Dn, mlp_b + i * Dn);
        gemm_tf32<0,1><<<gridFc, 256, 0, s1>>>(mlph, Wfci, hid, MLAT, INTERn, Dn,
                                               nullptr, nullptr, nullptr);
        gemm_tf32<0,2><<<gridWo, 256, 0, s1>>>(hid, Wcpi, lat, MLAT, Dn, INTERn,
                                               nullptr, nullptr, lat);
    }

    // join stream1 back into the capture-origin stream
    cudaEventRecord(evLat, s1);
    cudaStreamWaitEvent(0, evLat, 0);
    ln_kernel<true><<<MLAT, 256>>>(lat, out, f_g, f_b);
}

// round 16
// speedup vs baseline: 1.1070x; 1.0176x over previous
#include <cuda_runtime.h>
#include <cuda_bf16.h>
#include <math.h>

// ---------------- problem constants ----------------
#define Bn     32
#define Sn     2304
#define Dn     1280
#define Hn     16
#define HDn    96
#define HHD    1536      // Hn*HDn
#define Ln     64
#define INTERn 5120
#define DEPTHn 6
#define EPSf   1e-5f

// ---------------- scratch: __device__ globals (no cudaMalloc allowed) ----------------
__device__ float g_xhat[(size_t)Bn*Sn*Dn];        // normalized context (layer-independent)
__device__ float g_lat [(size_t)Bn*Ln*Dn];        // latent residual stream
__device__ float g_lhat[(size_t)Bn*Ln*Dn];
__device__ float g_mlph[(size_t)Bn*Ln*Dn];
__device__ float g_Kc  [2][(size_t)Bn*Sn*HHD];    // context K, double-buffered by layer parity
__device__ float g_Vc  [2][(size_t)Bn*Sn*HHD];    // context V, double-buffered
__device__ float g_Q   [(size_t)Bn*Ln*HHD];
__device__ float g_Kl  [(size_t)Bn*Ln*HHD];
__device__ float g_Vl  [(size_t)Bn*Ln*HHD];
__device__ float g_att [(size_t)Bn*Ln*HHD];
__device__ float g_hid [(size_t)Bn*Ln*INTERn];

// ---------------- helpers ----------------
__device__ __forceinline__ unsigned f2tf(float x) {
    unsigned r;
    asm("cvt.rna.tf32.f32 %0, %1;" : "=r"(r) : "f"(x));
    return r;
}

__device__ __forceinline__ void mma_tf32(float* c, const unsigned* a, const unsigned* b) {
    asm volatile(
        "mma.sync.aligned.m16n8k8.row.col.f32.tf32.tf32.f32 "
        "{%0,%1,%2,%3}, {%4,%5,%6,%7}, {%8,%9}, {%0,%1,%2,%3};\n"
        : "+f"(c[0]), "+f"(c[1]), "+f"(c[2]), "+f"(c[3])
        : "r"(a[0]), "r"(a[1]), "r"(a[2]), "r"(a[3]), "r"(b[0]), "r"(b[1]));
}

// ---------------- row LayerNorm, width = 1280 ----------------
template<bool AFF>
__global__ __launch_bounds__(256) void ln_kernel(
    const float* __restrict__ in, float* __restrict__ out,
    const float* __restrict__ g, const float* __restrict__ b)
{
    __shared__ float row[Dn];
    __shared__ float red[8];
    __shared__ float stat[2];
    const int r = blockIdx.x, tid = threadIdx.x;
    const int lane = tid & 31, w = tid >> 5;
    const float* x = in + (size_t)r * Dn;

    float s = 0.f;
    for (int i = tid; i < Dn; i += 256) { float v = x[i]; row[i] = v; s += v; }
    #pragma unroll
    for (int o = 16; o; o >>= 1) s += __shfl_xor_sync(0xffffffffu, s, o);
    if (lane == 0) red[w] = s;
    __syncthreads();
    if (tid == 0) { float t = 0.f; for (int j = 0; j < 8; j++) t += red[j]; stat[0] = t * (1.f/Dn); }
    __syncthreads();
    const float mean = stat[0];

    float s2 = 0.f;
    for (int i = tid; i < Dn; i += 256) { float d = row[i] - mean; s2 += d * d; }
    #pragma unroll
    for (int o = 16; o; o >>= 1) s2 += __shfl_xor_sync(0xffffffffu, s2, o);
    if (lane == 0) red[w] = s2;
    __syncthreads();
    if (tid == 0) { float t = 0.f; for (int j = 0; j < 8; j++) t += red[j]; stat[1] = rsqrtf(t * (1.f/Dn) + EPSf); }
    __syncthreads();
    const float rstd = stat[1];

    float* o = out + (size_t)r * Dn;
    for (int i = tid; i < Dn; i += 256) {
        float v = (row[i] - mean) * rstd;
        o[i] = AFF ? (v * g[i] + b[i]) : v;
    }
}

// ---------------- broadcast latents to batch ----------------
__global__ void bcast_lat(const float* __restrict__ lat0, float* __restrict__ out) {
    int i = blockIdx.x * 256 + threadIdx.x;
    if (i < Bn * Ln * Dn) out[i] = lat0[i % (Ln * Dn)];
}

// ---------------- TF32 GEMM body (R12-proven): C[M,N] = A[M,K] @ B[K,N] ----------------
// MODE_A: 0 plain, 1 per-column affine on A (a*g[k]+b[k]); EPI: 0 none, 1 relu, 2 +res
#define BM 128
#define BN 128
#define BK 32
#define PADA_K (BK + 4)   // 36: frag bank 4*(lane>>2)+(lane&3), conflict-free; STS.128 staging conflict-free
#define PADB (BN + 8)     // 136: frag bank 8*(lane&3)+(lane>>2), conflict-free

template<int MODE_A, int EPI>
__device__ __forceinline__ void gemm_body(
    const float* __restrict__ A, const float* __restrict__ B, float* __restrict__ C,
    int M, int N, int K,
    const float* __restrict__ ga, const float* __restrict__ ba,
    const float* __restrict__ res)
{
    __shared__ unsigned As[BM][PADA_K];
    __shared__ unsigned Bs[BK][PADB];
    __shared__ float gsh[MODE_A ? 1280 : 1];
    __shared__ float bsh[MODE_A ? 1280 : 1];

    const int tid  = threadIdx.x;
    const int lane = tid & 31;
    const int warp = tid >> 5;
    const int warpM = (warp >> 2) * 64;
    const int warpN = (warp & 3) * 32;

    const int nTilesN = N / BN;
    const int bidn = blockIdx.x % nTilesN;
    const int bidm = blockIdx.x / nTilesN;

    const float* Ablk = A + (size_t)bidm * BM * K;
    const float* Bblk = B + (size_t)bidn * BN;

    if (MODE_A) {
        for (int i = tid; i < K; i += 256) { gsh[i] = ga[i]; bsh[i] = ba[i]; }
    }

    float acc[4][4][4];
    #pragma unroll
    for (int i = 0; i < 4; i++)
        #pragma unroll
        for (int j = 0; j < 4; j++)
            #pragma unroll
            for (int q = 0; q < 4; q++) acc[i][j][q] = 0.f;

    if (MODE_A) __syncthreads();

    for (int k0 = 0; k0 < K; k0 += BK) {
        __syncthreads();
        #pragma unroll
        for (int it = 0; it < 4; it++) {
            int s = tid + it * 256;
            int rrow = s >> 3;
            int kq = (s & 7) * 4;
            float4 va = *(const float4*)(Ablk + (size_t)rrow * K + k0 + kq);
            if (MODE_A) {
                va.x = va.x * gsh[k0 + kq + 0] + bsh[k0 + kq + 0];
                va.y = va.y * gsh[k0 + kq + 1] + bsh[k0 + kq + 1];
                va.z = va.z * gsh[k0 + kq + 2] + bsh[k0 + kq + 2];
                va.w = va.w * gsh[k0 + kq + 3] + bsh[k0 + kq + 3];
            }
            uint4 ua;
            ua.x = f2tf(va.x); ua.y = f2tf(va.y); ua.z = f2tf(va.z); ua.w = f2tf(va.w);
            *(uint4*)&As[rrow][kq] = ua;
        }
        #pragma unroll
        for (int it = 0; it < 4; it++) {
            int s = tid + it * 256;
            int kr = s >> 5;
            int nq = (s & 31) * 4;
            float4 vb = *(const float4*)(Bblk + (size_t)(k0 + kr) * N + nq);
            uint4 ub;
            ub.x = f2tf(vb.x); ub.y = f2tf(vb.y); ub.z = f2tf(vb.z); ub.w = f2tf(vb.w);
            *(uint4*)&Bs[kr][nq] = ub;
        }
        __syncthreads();

        #pragma unroll
        for (int ks = 0; ks < 4; ks++) {
            unsigned af[4][4];
            unsigned bf[4][2];
            const int c = ks * 8 + (lane & 3);
            const int rbase = warpM + (lane >> 2);
            #pragma unroll
            for (int mt = 0; mt < 4; mt++) {
                int r = rbase + mt * 16;
                af[mt][0] = As[r][c];
                af[mt][1] = As[r + 8][c];
                af[mt][2] = As[r][c + 4];
                af[mt][3] = As[r + 8][c + 4];
            }
            const int cbase = warpN + (lane >> 2);
            #pragma unroll
            for (int nt = 0; nt < 4; nt++) {
                int cc = cbase + nt * 8;
                bf[nt][0] = Bs[c][cc];
                bf[nt][1] = Bs[c + 4][cc];
            }
            #pragma unroll
            for (int mt = 0; mt < 4; mt++)
                #pragma unroll
                for (int nt = 0; nt < 4; nt++)
                    mma_tf32(acc[mt][nt], af[mt], bf[nt]);
        }
    }

    #pragma unroll
    for (int mt = 0; mt < 4; mt++) {
        int r = bidm * BM + warpM + mt * 16 + (lane >> 2);
        #pragma unroll
        for (int nt = 0; nt < 4; nt++) {
            int cc = bidn * BN + warpN + nt * 8 + 2 * (lane & 3);
            float v00 = acc[mt][nt][0], v01 = acc[mt][nt][1];
            float v10 = acc[mt][nt][2], v11 = acc[mt][nt][3];
            if (EPI == 1) {
                v00 = fmaxf(v00, 0.f); v01 = fmaxf(v01, 0.f);
                v10 = fmaxf(v10, 0.f); v11 = fmaxf(v11, 0.f);
            }
            if (EPI == 2) {
                v00 += res[(size_t)r * N + cc];
                v01 += res[(size_t)r * N + cc + 1];
                v10 += res[(size_t)(r + 8) * N + cc];
                v11 += res[(size_t)(r + 8) * N + cc + 1];
            }
            C[(size_t)r * N + cc]           = v00;
            C[(size_t)r * N + cc + 1]       = v01;
            C[(size_t)(r + 8) * N + cc]     = v10;
            C[(size_t)(r + 8) * N + cc + 1] = v11;
        }
    }
}

template<int MODE_A, int EPI>
__global__ __launch_bounds__(256) void gemm_tf32(
    const float* __restrict__ A, const float* __restrict__ B, float* __restrict__ C,
    int M, int N, int K,
    const float* __restrict__ ga, const float* __restrict__ ba,
    const float* __restrict__ res)
{
    gemm_body<MODE_A, EPI>(A, B, C, M, N, K, ga, ba, res);
}

// combined context K+V projection: blockIdx.z selects (Wk->Kc) or (Wv->Vc)
__global__ __launch_bounds__(256) void gemm_kv(
    const float* __restrict__ A,
    const float* __restrict__ Wk, const float* __restrict__ Wv,
    float* __restrict__ Kc, float* __restrict__ Vc,
    int M, int N, int K,
    const float* __restrict__ ga, const float* __restrict__ ba)
{
    const float* B = (blockIdx.z == 0) ? Wk : Wv;
    float* C       = (blockIdx.z == 0) ? Kc : Vc;
    gemm_body<1, 0>(A, B, C, M, N, K, ga, ba, nullptr);
}

// batched latent QKV: blockIdx.z selects (W, C) pair
__global__ __launch_bounds__(256) void gemm_qkv(
    const float* __restrict__ A,
    const float* __restrict__ W0, const float* __restrict__ W1, const float* __restrict__ W2,
    float* __restrict__ C0, float* __restrict__ C1, float* __restrict__ C2,
    int M, int N, int K)
{
    const float* B = (blockIdx.z == 0) ? W0 : (blockIdx.z == 1) ? W1 : W2;
    float* C       = (blockIdx.z == 0) ? C0 : (blockIdx.z == 1) ? C1 : C2;
    gemm_body<0, 0>(A, B, C, M, N, K, nullptr, nullptr, nullptr);
}

// ---------------- flash attention with folded Q/K head-LayerNorm ----------------
// One CTA per (b, h). Q[64,96] resident; 37 key tiles of 64 over concat(context, latents).
// Q and K are head-LayerNormed on the fly (2 threads per row, 48 elems each).
#define PQ 100   // stride mod 32 == 4
#define PK 100
#define PV 108   // stride mod 32 == 12: staging STS.128 and frag loads both conflict-free
#define PP 68
#define ATTN_SMEM ((64*(PQ + PK + PV + PP) + 192) * 4)

__global__ __launch_bounds__(128) void attn_kernel(
    const float* __restrict__ Qg, const float* __restrict__ Kc, const float* __restrict__ Kl,
    const float* __restrict__ Vc, const float* __restrict__ Vl, float* __restrict__ Og,
    const float* __restrict__ qg, const float* __restrict__ qb,
    const float* __restrict__ kg, const float* __restrict__ kb)
{
    extern __shared__ unsigned sm[];
    unsigned* Qs = sm;                 // [64][PQ]
    unsigned* Ks = Qs + 64 * PQ;       // [64][PK]
    unsigned* Vs = Ks + 64 * PK;       // [64][PV]
    unsigned* Ps = Vs + 64 * PV;       // [64][PP]
    float* ksg = (float*)(Ps + 64 * PP);   // [96]
    float* ksb = ksg + 96;                 // [96]

    const int b = blockIdx.x / Hn;
    const int h = blockIdx.x % Hn;
    const int tid = threadIdx.x;
    const int warp = tid >> 5, lane = tid & 31;
    const float scale = 0.10206207261596577f;  // 96^-0.5
    const int row = tid >> 1;          // 0..63
    const int off48 = (tid & 1) * 48;  // element offset of this thread's half-row

    if (tid < 96) { ksg[tid] = kg[tid]; ksb[tid] = kb[tid]; }

    // ---- Q: load, head-LN (pair reduction), scale, tf32 ----
    {
        const float* src = Qg + (size_t)(b * Ln + row) * HHD + h * HDn + off48;
        float4 qv[12];
        float s = 0.f;
        #pragma unroll
        for (int j = 0; j < 12; j++) {
            qv[j] = *(const float4*)(src + j * 4);
            s += qv[j].x + qv[j].y + qv[j].z + qv[j].w;
        }
        s += __shfl_xor_sync(0xffffffffu, s, 1);
        const float mean = s * (1.f / HDn);
        float v2 = 0.f;
        #pragma unroll
        for (int j = 0; j < 12; j++) {
            float d0 = qv[j].x - mean, d1 = qv[j].y - mean;
            float d2 = qv[j].z - mean, d3 = qv[j].w - mean;
            v2 += d0 * d0 + d1 * d1 + d2 * d2 + d3 * d3;
        }
        v2 += __shfl_xor_sync(0xffffffffu, v2, 1);
        const float rstd = rsqrtf(v2 * (1.f / HDn) + EPSf);
        #pragma unroll
        for (int j = 0; j < 12; j++) {
            const int e = off48 + j * 4;
            uint4 u;
            u.x = f2tf(((qv[j].x - mean) * rstd * qg[e + 0] + qb[e + 0]) * scale);
            u.y = f2tf(((qv[j].y - mean) * rstd * qg[e + 1] + qb[e + 1]) * scale);
            u.z = f2tf(((qv[j].z - mean) * rstd * qg[e + 2] + qb[e + 2]) * scale);
            u.w = f2tf(((qv[j].w - mean) * rstd * qg[e + 3] + qb[e + 3]) * scale);
            *(uint4*)&Qs[row * PQ + e] = u;
        }
    }

    float o[12][4];
    #pragma unroll
    for (int i = 0; i < 12; i++) { o[i][0] = o[i][1] = o[i][2] = o[i][3] = 0.f; }
    float m0 = -1e30f, m1 = -1e30f, l0 = 0.f, l1 = 0.f;

    const int r0loc = warp * 16 + (lane >> 2);
    const int nTiles = (Sn + Ln) / 64;   // 37

    for (int t = 0; t < nTiles; t++) {
        __syncthreads();   // protects K/V smem reuse; first iter also fences ksg/Qs
        const int gk = t * 64 + row;

        // ---- K: load + head-LN + tf32 ----
        {
            const float* srck = (gk < Sn)
                ? (Kc + (size_t)(b * Sn + gk) * HHD + h * HDn + off48)
                : (Kl + (size_t)(b * Ln + gk - Sn) * HHD + h * HDn + off48);
            float4 kv[12];
            float s = 0.f;
            #pragma unroll
            for (int j = 0; j < 12; j++) {
                kv[j] = *(const float4*)(srck + j * 4);
                s += kv[j].x + kv[j].y + kv[j].z + kv[j].w;
            }
            s += __shfl_xor_sync(0xffffffffu, s, 1);
            const float mean = s * (1.f / HDn);
            float v2 = 0.f;
            #pragma unroll
            for (int j = 0; j < 12; j++) {
                float d0 = kv[j].x - mean, d1 = kv[j].y - mean;
                float d2 = kv[j].z - mean, d3 = kv[j].w - mean;
                v2 += d0 * d0 + d1 * d1 + d2 * d2 + d3 * d3;
            }
            v2 += __shfl_xor_sync(0xffffffffu, v2, 1);
            const float rstd = rsqrtf(v2 * (1.f / HDn) + EPSf);
            #pragma unroll
            for (int j = 0; j < 12; j++) {
                const int e = off48 + j * 4;
                uint4 u;
                u.x = f2tf((kv[j].x - mean) * rstd * ksg[e + 0] + ksb[e + 0]);
                u.y = f2tf((kv[j].y - mean) * rstd * ksg[e + 1] + ksb[e + 1]);
                u.z = f2tf((kv[j].z - mean) * rstd * ksg[e + 2] + ksb[e + 2]);
                u.w = f2tf((kv[j].w - mean) * rstd * ksg[e + 3] + ksb[e + 3]);
                *(uint4*)&Ks[row * PK + e] = u;
            }
        }
        // ---- V: plain load + tf32 ----
        {
            const float* srcv = (gk < Sn)
                ? (Vc + (size_t)(b * Sn + gk) * HHD + h * HDn + off48)
                : (Vl + (size_t)(b * Ln + gk - Sn) * HHD + h * HDn + off48);
            #pragma unroll
            for (int j = 0; j < 12; j++) {
                float4 vv = *(const float4*)(srcv + j * 4);
                uint4 u;
                u.x = f2tf(vv.x); u.y = f2tf(vv.y); u.z = f2tf(vv.z); u.w = f2tf(vv.w);
                *(uint4*)&Vs[row * PV + off48 + j * 4] = u;
            }
        }
        __syncthreads();

        // S = Q @ K^T
        float sf[8][4];
        #pragma unroll
        for (int nt = 0; nt < 8; nt++) { sf[nt][0] = sf[nt][1] = sf[nt][2] = sf[nt][3] = 0.f; }
        #pragma unroll
        for (int ks = 0; ks < 12; ks++) {
            const int c = ks * 8 + (lane & 3);
            unsigned a[4];
            a[0] = Qs[r0loc * PQ + c];
            a[1] = Qs[(r0loc + 8) * PQ + c];
            a[2] = Qs[r0loc * PQ + c + 4];
            a[3] = Qs[(r0loc + 8) * PQ + c + 4];
            #pragma unroll
            for (int nt = 0; nt < 8; nt++) {
                unsigned bb[2];
                int key = nt * 8 + (lane >> 2);
                bb[0] = Ks[key * PK + c];
                bb[1] = Ks[key * PK + c + 4];
                mma_tf32(sf[nt], a, bb);
            }
        }

        // online softmax
        float mt0 = -1e30f, mt1 = -1e30f;
        #pragma unroll
        for (int nt = 0; nt < 8; nt++) {
            mt0 = fmaxf(mt0, fmaxf(sf[nt][0], sf[nt][1]));
            mt1 = fmaxf(mt1, fmaxf(sf[nt][2], sf[nt][3]));
        }
        mt0 = fmaxf(mt0, __shfl_xor_sync(0xffffffffu, mt0, 1));
        mt0 = fmaxf(mt0, __shfl_xor_sync(0xffffffffu, mt0, 2));
        mt1 = fmaxf(mt1, __shfl_xor_sync(0xffffffffu, mt1, 1));
        mt1 = fmaxf(mt1, __shfl_xor_sync(0xffffffffu, mt1, 2));
        const float mn0 = fmaxf(m0, mt0), mn1 = fmaxf(m1, mt1);
        const float al0 = __expf(m0 - mn0), al1 = __expf(m1 - mn1);
        m0 = mn0; m1 = mn1;

        float ps0 = 0.f, ps1 = 0.f;
        #pragma unroll
        for (int nt = 0; nt < 8; nt++) {
            int cc = nt * 8 + 2 * (lane & 3);
            float p00 = __expf(sf[nt][0] - mn0);
            float p01 = __expf(sf[nt][1] - mn0);
            float p10 = __expf(sf[nt][2] - mn1);
            float p11 = __expf(sf[nt][3] - mn1);
            ps0 += p00 + p01;
            ps1 += p10 + p11;
            Ps[r0loc * PP + cc]           = f2tf(p00);
            Ps[r0loc * PP + cc + 1]       = f2tf(p01);
            Ps[(r0loc + 8) * PP + cc]     = f2tf(p10);
            Ps[(r0loc + 8) * PP + cc + 1] = f2tf(p11);
        }
        ps0 += __shfl_xor_sync(0xffffffffu, ps0, 1);
        ps0 += __shfl_xor_sync(0xffffffffu, ps0, 2);
        ps1 += __shfl_xor_sync(0xffffffffu, ps1, 1);
        ps1 += __shfl_xor_sync(0xffffffffu, ps1, 2);
        l0 = l0 * al0 + ps0;
        l1 = l1 * al1 + ps1;

        #pragma unroll
        for (int i = 0; i < 12; i++) {
            o[i][0] *= al0; o[i][1] *= al0;
            o[i][2] *= al1; o[i][3] *= al1;
        }
        __syncwarp();

        // O += P @ V
        #pragma unroll
        for (int ks = 0; ks < 8; ks++) {
            const int kk = ks * 8 + (lane & 3);
            unsigned a[4];
            a[0] = Ps[r0loc * PP + kk];
            a[1] = Ps[(r0loc + 8) * PP + kk];
            a[2] = Ps[r0loc * PP + kk + 4];
            a[3] = Ps[(r0loc + 8) * PP + kk + 4];
            #pragma unroll
            for (int nt = 0; nt < 12; nt++) {
                unsigned bb[2];
                int n = nt * 8 + (lane >> 2);
                bb[0] = Vs[kk * PV + n];
                bb[1] = Vs[(kk + 4) * PV + n];
                mma_tf32(o[nt], a, bb);
            }
        }
    }

    const float inv0 = 1.f / l0, inv1 = 1.f / l1;
    #pragma unroll
    for (int nt = 0; nt < 12; nt++) {
        int cc = nt * 8 + 2 * (lane & 3);
        size_t base0 = (size_t)(b * Ln + r0loc) * HHD + h * HDn + cc;
        size_t base1 = (size_t)(b * Ln + r0loc + 8) * HHD + h * HDn + cc;
        Og[base0]     = o[nt][0] * inv0;
        Og[base0 + 1] = o[nt][1] * inv0;
        Og[base1]     = o[nt][2] * inv1;
        Og[base1 + 1] = o[nt][3] * inv1;
    }
}

// ---------------- host orchestration ----------------
extern "C" void kernel_launch(void* const* d_in, const int* in_sizes, int n_in,
                              void* d_out, int out_size)
{
    const float* context = (const float*)d_in[0];
    const float* latents = (const float*)d_in[1];
    const float* ctx_g   = (const float*)d_in[2];
    const float* ctx_b   = (const float*)d_in[3];
    const float* lat_g   = (const float*)d_in[4];
    const float* lat_b   = (const float*)d_in[5];
    const float* q_g     = (const float*)d_in[6];
    const float* q_b     = (const float*)d_in[7];
    const float* k_g     = (const float*)d_in[8];
    const float* k_b     = (const float*)d_in[9];
    const float* Wq      = (const float*)d_in[10];
    const float* Wk      = (const float*)d_in[11];
    const float* Wv      = (const float*)d_in[12];
    const float* Wo      = (const float*)d_in[13];
    const float* mlp_g   = (const float*)d_in[14];
    const float* mlp_b   = (const float*)d_in[15];
    const float* Wfc     = (const float*)d_in[16];
    const float* Wcp     = (const float*)d_in[17];
    const float* f_g     = (const float*)d_in[18];
    const float* f_b     = (const float*)d_in[19];
    float* out = (float*)d_out;

    float *xhat, *lat, *lhat, *mlph, *Kc0, *Vc0, *Qb, *Kl, *Vl, *att, *hid;
    cudaGetSymbolAddress((void**)&xhat, g_xhat);
    cudaGetSymbolAddress((void**)&lat,  g_lat);
    cudaGetSymbolAddress((void**)&lhat, g_lhat);
    cudaGetSymbolAddress((void**)&mlph, g_mlph);
    cudaGetSymbolAddress((void**)&Kc0,  g_Kc);
    cudaGetSymbolAddress((void**)&Vc0,  g_Vc);
    cudaGetSymbolAddress((void**)&Qb,   g_Q);
    cudaGetSymbolAddress((void**)&Kl,   g_Kl);
    cudaGetSymbolAddress((void**)&Vl,   g_Vl);
    cudaGetSymbolAddress((void**)&att,  g_att);
    cudaGetSymbolAddress((void**)&hid,  g_hid);
    const size_t KV_STRIDE = (size_t)Bn * Sn * HHD;

    cudaFuncSetAttribute(attn_kernel, cudaFuncAttributeMaxDynamicSharedMemorySize, ATTN_SMEM);

    // one-time stream/event setup (host resources, not device memory).
    // s1 = HIGH priority: latent/attention CTAs preempt the deep big-GEMM queue.
    static cudaStream_t s1 = nullptr;
    static cudaEvent_t ev0, evLat, evKV[DEPTHn], evAttn[DEPTHn];
    if (s1 == nullptr) {
        int prLo, prHi;
        cudaDeviceGetStreamPriorityRange(&prLo, &prHi);
        cudaStreamCreateWithPriority(&s1, cudaStreamNonBlocking, prHi);
        cudaEventCreateWithFlags(&ev0, cudaEventDisableTiming);
        cudaEventCreateWithFlags(&evLat, cudaEventDisableTiming);
        for (int i = 0; i < DEPTHn; i++) {
            cudaEventCreateWithFlags(&evKV[i], cudaEventDisableTiming);
            cudaEventCreateWithFlags(&evAttn[i], cudaEventDisableTiming);
        }
    }

    const int MBIG = Bn * Sn;   // 73728
    const int MLAT = Bn * Ln;   // 2048
    const int gridBig = (MBIG / BM) * (HHD / BN);       // 6912 (x2 in z for K+V)
    const int gridQKV = (MLAT / BM) * (HHD / BN);       // 192 (x3 in z)
    const int gridWo  = (MLAT / BM) * (Dn / BN);        // 160
    const int gridFc  = (MLAT / BM) * (INTERn / BN);    // 640

    // fork s1 from the capture-origin stream FIRST (graph-capture requirement),
    // then start independent work on both streams immediately:
    //   s0: context LN (xhat) -> big K/V GEMMs
    //   s1: latent broadcast -> per-layer latent chain
    cudaEventRecord(ev0, 0);
    cudaStreamWaitEvent(s1, ev0, 0);

    ln_kernel<false><<<MBIG, 256>>>(context, xhat, nullptr, nullptr);
    bcast_lat<<<(Bn * Ln * Dn + 255) / 256, 256, 0, s1>>>(latents, lat);

    for (int i = 0; i < DEPTHn; i++) {
        const int p = i & 1;
        float* Kc = Kc0 + p * KV_STRIDE;
        float* Vc = Vc0 + p * KV_STRIDE;
        const float* Wqi  = Wq  + (size_t)i * Dn * HHD;
        const float* Wki  = Wk  + (size_t)i * Dn * HHD;
        const float* Wvi  = Wv  + (size_t)i * Dn * HHD;
        const float* Woi  = Wo  + (size_t)i * HHD * Dn;
        const float* Wfci = Wfc + (size_t)i * Dn * INTERn;
        const float* Wcpi = Wcp + (size_t)i * INTERn * Dn;

        // ---- stream0: combined big context K+V GEMM (buffer parity p; reuse guarded) ----
        if (i >= 2) cudaStreamWaitEvent(0, evAttn[i - 2], 0);
        gemm_kv<<<dim3(gridBig, 1, 2), 256>>>(xhat, Wki, Wvi, Kc, Vc, MBIG, HHD, Dn,
                                              ctx_g + i * Dn, ctx_b + i * Dn);
        cudaEventRecord(evKV[i], 0);

        // ---- stream1 (high priority): latent chain ----
        ln_kernel<true><<<MLAT, 256, 0, s1>>>(lat, lhat, lat_g + i * Dn, lat_b + i * Dn);
        gemm_qkv<<<dim3(gridQKV, 1, 3), 256, 0, s1>>>(lhat, Wqi, Wki, Wvi,
                                                      Qb, Kl, Vl, MLAT, HHD, Dn);
        cudaStreamWaitEvent(s1, evKV[i], 0);
        attn_kernel<<<Bn * Hn, 128, ATTN_SMEM, s1>>>(Qb, Kc, Kl, Vc, Vl, att,
                                                     q_g + i * HDn, q_b + i * HDn,
                                                     k_g + i * HDn, k_b + i * HDn);
        cudaEventRecord(evAttn[i], s1);
        gemm_tf32<0,2><<<gridWo, 256, 0, s1>>>(att, Woi, lat, MLAT, Dn, HHD,
                                               nullptr, nullptr, lat);
        ln_kernel<true><<<MLAT, 256, 0, s1>>>(lat, mlph, mlp_g + i * Dn, mlp_b + i * Dn);
        gemm_tf32<0,1><<<gridFc, 256, 0, s1>>>(mlph, Wfci, hid, MLAT, INTERn, Dn,
                                               nullptr, nullptr, nullptr);
        gemm_tf32<0,2><<<gridWo, 256, 0, s1>>>(hid, Wcpi, lat, MLAT, Dn, INTERn,
                                               nullptr, nullptr, lat);
    }

    // join stream1 back into the capture-origin stream
    cudaEventRecord(evLat, s1);
    cudaStreamWaitEvent(0, evLat, 0);
    ln_kernel<true><<<MLAT, 256>>>(lat, out, f_g, f_b);
}

// round 17
// speedup vs baseline: 1.2524x; 1.1313x over previous
#include <cuda_runtime.h>
#include <cuda_bf16.h>
#include <cuda_fp16.h>
#include <math.h>

// ---------------- problem constants ----------------
#define Bn     32
#define Sn     2304
#define Dn     1280
#define Hn     16
#define HDn    96
#define HHD    1536      // Hn*HDn
#define Ln     64
#define INTERn 5120
#define DEPTHn 6
#define EPSf   1e-5f

// ---------------- scratch: __device__ globals (no cudaMalloc allowed) ----------------
__device__ float g_xhat[(size_t)Bn*Sn*Dn];        // normalized context (layer-independent)
__device__ float g_lat [(size_t)Bn*Ln*Dn];        // latent residual stream
__device__ float g_lhat[(size_t)Bn*Ln*Dn];
__device__ float g_mlph[(size_t)Bn*Ln*Dn];
__device__ float g_Kc  [2][(size_t)Bn*Sn*HHD];    // context K, double-buffered by layer parity
__device__ float g_Vc  [2][(size_t)Bn*Sn*HHD];    // context V, double-buffered
__device__ float g_Q   [(size_t)Bn*Ln*HHD];
__device__ float g_Kl  [(size_t)Bn*Ln*HHD];
__device__ float g_Vl  [(size_t)Bn*Ln*HHD];
__device__ float g_att [(size_t)Bn*Ln*HHD];
__device__ float g_hid [(size_t)Bn*Ln*INTERn];

// ---------------- helpers ----------------
__device__ __forceinline__ unsigned f2tf(float x) {
    unsigned r;
    asm("cvt.rna.tf32.f32 %0, %1;" : "=r"(r) : "f"(x));
    return r;
}

__device__ __forceinline__ void mma_tf32(float* c, const unsigned* a, const unsigned* b) {
    asm volatile(
        "mma.sync.aligned.m16n8k8.row.col.f32.tf32.tf32.f32 "
        "{%0,%1,%2,%3}, {%4,%5,%6,%7}, {%8,%9}, {%0,%1,%2,%3};\n"
        : "+f"(c[0]), "+f"(c[1]), "+f"(c[2]), "+f"(c[3])
        : "r"(a[0]), "r"(a[1]), "r"(a[2]), "r"(a[3]), "r"(b[0]), "r"(b[1]));
}

// fp16 MMA: D[16x8] += A[16x16] * B[16x8], fp32 accumulate
__device__ __forceinline__ void mma_f16(float* c, const unsigned* a, const unsigned* b) {
    asm volatile(
        "mma.sync.aligned.m16n8k16.row.col.f32.f16.f16.f32 "
        "{%0,%1,%2,%3}, {%4,%5,%6,%7}, {%8,%9}, {%0,%1,%2,%3};\n"
        : "+f"(c[0]), "+f"(c[1]), "+f"(c[2]), "+f"(c[3])
        : "r"(a[0]), "r"(a[1]), "r"(a[2]), "r"(a[3]), "r"(b[0]), "r"(b[1]));
}

__device__ __forceinline__ unsigned pack_h2(float lo, float hi) {
    __half2 h = __floats2half2_rn(lo, hi);
    return *(unsigned*)&h;
}

// ---------------- row LayerNorm, width = 1280 ----------------
template<bool AFF>
__global__ __launch_bounds__(256) void ln_kernel(
    const float* __restrict__ in, float* __restrict__ out,
    const float* __restrict__ g, const float* __restrict__ b)
{
    __shared__ float row[Dn];
    __shared__ float red[8];
    __shared__ float stat[2];
    const int r = blockIdx.x, tid = threadIdx.x;
    const int lane = tid & 31, w = tid >> 5;
    const float* x = in + (size_t)r * Dn;

    float s = 0.f;
    for (int i = tid; i < Dn; i += 256) { float v = x[i]; row[i] = v; s += v; }
    #pragma unroll
    for (int o = 16; o; o >>= 1) s += __shfl_xor_sync(0xffffffffu, s, o);
    if (lane == 0) red[w] = s;
    __syncthreads();
    if (tid == 0) { float t = 0.f; for (int j = 0; j < 8; j++) t += red[j]; stat[0] = t * (1.f/Dn); }
    __syncthreads();
    const float mean = stat[0];

    float s2 = 0.f;
    for (int i = tid; i < Dn; i += 256) { float d = row[i] - mean; s2 += d * d; }
    #pragma unroll
    for (int o = 16; o; o >>= 1) s2 += __shfl_xor_sync(0xffffffffu, s2, o);
    if (lane == 0) red[w] = s2;
    __syncthreads();
    if (tid == 0) { float t = 0.f; for (int j = 0; j < 8; j++) t += red[j]; stat[1] = rsqrtf(t * (1.f/Dn) + EPSf); }
    __syncthreads();
    const float rstd = stat[1];

    float* o = out + (size_t)r * Dn;
    for (int i = tid; i < Dn; i += 256) {
        float v = (row[i] - mean) * rstd;
        o[i] = AFF ? (v * g[i] + b[i]) : v;
    }
}

// ---------------- broadcast latents to batch ----------------
__global__ void bcast_lat(const float* __restrict__ lat0, float* __restrict__ out) {
    int i = blockIdx.x * 256 + threadIdx.x;
    if (i < Bn * Ln * Dn) out[i] = lat0[i % (Ln * Dn)];
}

// ---------------- FP16 GEMM body: C[M,N] = A[M,K] @ B[K,N] ----------------
// smem stages raw fp32; conversion to fp16 happens at fragment load (rn).
// MODE_A: 0 plain, 1 per-column affine on A (a*g[k]+b[k]); EPI: 0 none, 1 relu, 2 +res
#define BM 128
#define BN 128
#define BK 32
// A [BM][PADA] floats, stride 40 words (mod 32 = 8):
//   frag LDS.64 at [r][2*(l&3)] (+8): half-warp banks 8*(l>>2)+2*(l&3)+{0,1} -> all 32, conflict-free
//   staging float4: quarter-warp covers 32 consecutive-ish banks, conflict-free
#define PADA (BK + 8)     // 40
// B [BK][PADB] floats, stride 132 words (264 mod 32 = 8 for 2-row step):
//   frag LDS.32 at [2*(l&3)][cc]: banks 8*(l&3)+(l>>2)+c -> all 32, conflict-free (also +1, +8 rows)
//   staging float4: kr constant per warp, consecutive words, conflict-free
#define PADB (BN + 4)     // 132

template<int MODE_A, int EPI>
__device__ __forceinline__ void gemm_body(
    const float* __restrict__ A, const float* __restrict__ B, float* __restrict__ C,
    int M, int N, int K,
    const float* __restrict__ ga, const float* __restrict__ ba,
    const float* __restrict__ res)
{
    __shared__ __align__(16) float As[BM][PADA];
    __shared__ __align__(16) float Bs[BK][PADB];
    __shared__ float gsh[MODE_A ? 1280 : 1];
    __shared__ float bsh[MODE_A ? 1280 : 1];

    const int tid  = threadIdx.x;
    const int lane = tid & 31;
    const int warp = tid >> 5;
    const int warpM = (warp >> 2) * 64;
    const int warpN = (warp & 3) * 32;

    const int nTilesN = N / BN;
    const int bidn = blockIdx.x % nTilesN;
    const int bidm = blockIdx.x / nTilesN;

    const float* Ablk = A + (size_t)bidm * BM * K;
    const float* Bblk = B + (size_t)bidn * BN;

    if (MODE_A) {
        for (int i = tid; i < K; i += 256) { gsh[i] = ga[i]; bsh[i] = ba[i]; }
    }

    float acc[4][4][4];
    #pragma unroll
    for (int i = 0; i < 4; i++)
        #pragma unroll
        for (int j = 0; j < 4; j++)
            #pragma unroll
            for (int q = 0; q < 4; q++) acc[i][j][q] = 0.f;

    if (MODE_A) __syncthreads();

    for (int k0 = 0; k0 < K; k0 += BK) {
        __syncthreads();
        // A tile: 128 rows x 32 k, raw fp32 (affine applied), STS.128
        #pragma unroll
        for (int it = 0; it < 4; it++) {
            int s = tid + it * 256;
            int rrow = s >> 3;
            int kq = (s & 7) * 4;
            float4 va = *(const float4*)(Ablk + (size_t)rrow * K + k0 + kq);
            if (MODE_A) {
                va.x = va.x * gsh[k0 + kq + 0] + bsh[k0 + kq + 0];
                va.y = va.y * gsh[k0 + kq + 1] + bsh[k0 + kq + 1];
                va.z = va.z * gsh[k0 + kq + 2] + bsh[k0 + kq + 2];
                va.w = va.w * gsh[k0 + kq + 3] + bsh[k0 + kq + 3];
            }
            *(float4*)&As[rrow][kq] = va;
        }
        // B tile: 32 k-rows x 128 n, raw fp32, STS.128
        #pragma unroll
        for (int it = 0; it < 4; it++) {
            int s = tid + it * 256;
            int kr = s >> 5;
            int nq = (s & 31) * 4;
            *(float4*)&Bs[kr][nq] = *(const float4*)(Bblk + (size_t)(k0 + kr) * N + nq);
        }
        __syncthreads();

        // 2 k16 MMA steps per 32-k tile
        #pragma unroll
        for (int ks = 0; ks < 2; ks++) {
            const int c = ks * 16 + 2 * (lane & 3);
            const int rbase = warpM + (lane >> 2);
            unsigned af[4][4];
            #pragma unroll
            for (int mt = 0; mt < 4; mt++) {
                int r = rbase + mt * 16;
                float2 p0 = *(const float2*)&As[r][c];
                float2 p1 = *(const float2*)&As[r + 8][c];
                float2 p2 = *(const float2*)&As[r][c + 8];
                float2 p3 = *(const float2*)&As[r + 8][c + 8];
                af[mt][0] = pack_h2(p0.x, p0.y);
                af[mt][1] = pack_h2(p1.x, p1.y);
                af[mt][2] = pack_h2(p2.x, p2.y);
                af[mt][3] = pack_h2(p3.x, p3.y);
            }
            const int cbase = warpN + (lane >> 2);
            unsigned bf[4][2];
            #pragma unroll
            for (int nt = 0; nt < 4; nt++) {
                int cc = cbase + nt * 8;
                bf[nt][0] = pack_h2(Bs[c][cc], Bs[c + 1][cc]);
                bf[nt][1] = pack_h2(Bs[c + 8][cc], Bs[c + 9][cc]);
            }
            #pragma unroll
            for (int mt = 0; mt < 4; mt++)
                #pragma unroll
                for (int nt = 0; nt < 4; nt++)
                    mma_f16(acc[mt][nt], af[mt], bf[nt]);
        }
    }

    #pragma unroll
    for (int mt = 0; mt < 4; mt++) {
        int r = bidm * BM + warpM + mt * 16 + (lane >> 2);
        #pragma unroll
        for (int nt = 0; nt < 4; nt++) {
            int cc = bidn * BN + warpN + nt * 8 + 2 * (lane & 3);
            float v00 = acc[mt][nt][0], v01 = acc[mt][nt][1];
            float v10 = acc[mt][nt][2], v11 = acc[mt][nt][3];
            if (EPI == 1) {
                v00 = fmaxf(v00, 0.f); v01 = fmaxf(v01, 0.f);
                v10 = fmaxf(v10, 0.f); v11 = fmaxf(v11, 0.f);
            }
            if (EPI == 2) {
                v00 += res[(size_t)r * N + cc];
                v01 += res[(size_t)r * N + cc + 1];
                v10 += res[(size_t)(r + 8) * N + cc];
                v11 += res[(size_t)(r + 8) * N + cc + 1];
            }
            C[(size_t)r * N + cc]           = v00;
            C[(size_t)r * N + cc + 1]       = v01;
            C[(size_t)(r + 8) * N + cc]     = v10;
            C[(size_t)(r + 8) * N + cc + 1] = v11;
        }
    }
}

template<int MODE_A, int EPI>
__global__ __launch_bounds__(256) void gemm_tf32(
    const float* __restrict__ A, const float* __restrict__ B, float* __restrict__ C,
    int M, int N, int K,
    const float* __restrict__ ga, const float* __restrict__ ba,
    const float* __restrict__ res)
{
    gemm_body<MODE_A, EPI>(A, B, C, M, N, K, ga, ba, res);
}

// combined context K+V projection: blockIdx.z selects (Wk->Kc) or (Wv->Vc)
__global__ __launch_bounds__(256) void gemm_kv(
    const float* __restrict__ A,
    const float* __restrict__ Wk, const float* __restrict__ Wv,
    float* __restrict__ Kc, float* __restrict__ Vc,
    int M, int N, int K,
    const float* __restrict__ ga, const float* __restrict__ ba)
{
    const float* B = (blockIdx.z == 0) ? Wk : Wv;
    float* C       = (blockIdx.z == 0) ? Kc : Vc;
    gemm_body<1, 0>(A, B, C, M, N, K, ga, ba, nullptr);
}

// batched latent QKV: blockIdx.z selects (W, C) pair
__global__ __launch_bounds__(256) void gemm_qkv(
    const float* __restrict__ A,
    const float* __restrict__ W0, const float* __restrict__ W1, const float* __restrict__ W2,
    float* __restrict__ C0, float* __restrict__ C1, float* __restrict__ C2,
    int M, int N, int K)
{
    const float* B = (blockIdx.z == 0) ? W0 : (blockIdx.z == 1) ? W1 : W2;
    float* C       = (blockIdx.z == 0) ? C0 : (blockIdx.z == 1) ? C1 : C2;
    gemm_body<0, 0>(A, B, C, M, N, K, nullptr, nullptr, nullptr);
}

// ---------------- flash attention with folded Q/K head-LayerNorm (tf32, unchanged) ----------------
#define PQ 100   // stride mod 32 == 4
#define PK 100
#define PV 108   // stride mod 32 == 12
#define PP 68
#define ATTN_SMEM ((64*(PQ + PK + PV + PP) + 192) * 4)

__global__ __launch_bounds__(128) void attn_kernel(
    const float* __restrict__ Qg, const float* __restrict__ Kc, const float* __restrict__ Kl,
    const float* __restrict__ Vc, const float* __restrict__ Vl, float* __restrict__ Og,
    const float* __restrict__ qg, const float* __restrict__ qb,
    const float* __restrict__ kg, const float* __restrict__ kb)
{
    extern __shared__ unsigned sm[];
    unsigned* Qs = sm;                 // [64][PQ]
    unsigned* Ks = Qs + 64 * PQ;       // [64][PK]
    unsigned* Vs = Ks + 64 * PK;       // [64][PV]
    unsigned* Ps = Vs + 64 * PV;       // [64][PP]
    float* ksg = (float*)(Ps + 64 * PP);   // [96]
    float* ksb = ksg + 96;                 // [96]

    const int b = blockIdx.x / Hn;
    const int h = blockIdx.x % Hn;
    const int tid = threadIdx.x;
    const int warp = tid >> 5, lane = tid & 31;
    const float scale = 0.10206207261596577f;  // 96^-0.5
    const int row = tid >> 1;
    const int off48 = (tid & 1) * 48;

    if (tid < 96) { ksg[tid] = kg[tid]; ksb[tid] = kb[tid]; }

    // ---- Q: load, head-LN (pair reduction), scale, tf32 ----
    {
        const float* src = Qg + (size_t)(b * Ln + row) * HHD + h * HDn + off48;
        float4 qv[12];
        float s = 0.f;
        #pragma unroll
        for (int j = 0; j < 12; j++) {
            qv[j] = *(const float4*)(src + j * 4);
            s += qv[j].x + qv[j].y + qv[j].z + qv[j].w;
        }
        s += __shfl_xor_sync(0xffffffffu, s, 1);
        const float mean = s * (1.f / HDn);
        float v2 = 0.f;
        #pragma unroll
        for (int j = 0; j < 12; j++) {
            float d0 = qv[j].x - mean, d1 = qv[j].y - mean;
            float d2 = qv[j].z - mean, d3 = qv[j].w - mean;
            v2 += d0 * d0 + d1 * d1 + d2 * d2 + d3 * d3;
        }
        v2 += __shfl_xor_sync(0xffffffffu, v2, 1);
        const float rstd = rsqrtf(v2 * (1.f / HDn) + EPSf);
        #pragma unroll
        for (int j = 0; j < 12; j++) {
            const int e = off48 + j * 4;
            uint4 u;
            u.x = f2tf(((qv[j].x - mean) * rstd * qg[e + 0] + qb[e + 0]) * scale);
            u.y = f2tf(((qv[j].y - mean) * rstd * qg[e + 1] + qb[e + 1]) * scale);
            u.z = f2tf(((qv[j].z - mean) * rstd * qg[e + 2] + qb[e + 2]) * scale);
            u.w = f2tf(((qv[j].w - mean) * rstd * qg[e + 3] + qb[e + 3]) * scale);
            *(uint4*)&Qs[row * PQ + e] = u;
        }
    }

    float o[12][4];
    #pragma unroll
    for (int i = 0; i < 12; i++) { o[i][0] = o[i][1] = o[i][2] = o[i][3] = 0.f; }
    float m0 = -1e30f, m1 = -1e30f, l0 = 0.f, l1 = 0.f;

    const int r0loc = warp * 16 + (lane >> 2);
    const int nTiles = (Sn + Ln) / 64;

    for (int t = 0; t < nTiles; t++) {
        __syncthreads();
        const int gk = t * 64 + row;

        {
            const float* srck = (gk < Sn)
                ? (Kc + (size_t)(b * Sn + gk) * HHD + h * HDn + off48)
                : (Kl + (size_t)(b * Ln + gk - Sn) * HHD + h * HDn + off48);
            float4 kv[12];
            float s = 0.f;
            #pragma unroll
            for (int j = 0; j < 12; j++) {
                kv[j] = *(const float4*)(srck + j * 4);
                s += kv[j].x + kv[j].y + kv[j].z + kv[j].w;
            }
            s += __shfl_xor_sync(0xffffffffu, s, 1);
            const float mean = s * (1.f / HDn);
            float v2 = 0.f;
            #pragma unroll
            for (int j = 0; j < 12; j++) {
                float d0 = kv[j].x - mean, d1 = kv[j].y - mean;
                float d2 = kv[j].z - mean, d3 = kv[j].w - mean;
                v2 += d0 * d0 + d1 * d1 + d2 * d2 + d3 * d3;
            }
            v2 += __shfl_xor_sync(0xffffffffu, v2, 1);
            const float rstd = rsqrtf(v2 * (1.f / HDn) + EPSf);
            #pragma unroll
            for (int j = 0; j < 12; j++) {
                const int e = off48 + j * 4;
                uint4 u;
                u.x = f2tf((kv[j].x - mean) * rstd * ksg[e + 0] + ksb[e + 0]);
                u.y = f2tf((kv[j].y - mean) * rstd * ksg[e + 1] + ksb[e + 1]);
                u.z = f2tf((kv[j].z - mean) * rstd * ksg[e + 2] + ksb[e + 2]);
                u.w = f2tf((kv[j].w - mean) * rstd * ksg[e + 3] + ksb[e + 3]);
                *(uint4*)&Ks[row * PK + e] = u;
            }
        }
        {
            const float* srcv = (gk < Sn)
                ? (Vc + (size_t)(b * Sn + gk) * HHD + h * HDn + off48)
                : (Vl + (size_t)(b * Ln + gk - Sn) * HHD + h * HDn + off48);
            #pragma unroll
            for (int j = 0; j < 12; j++) {
                float4 vv = *(const float4*)(srcv + j * 4);
                uint4 u;
                u.x = f2tf(vv.x); u.y = f2tf(vv.y); u.z = f2tf(vv.z); u.w = f2tf(vv.w);
                *(uint4*)&Vs[row * PV + off48 + j * 4] = u;
            }
        }
        __syncthreads();

        float sf[8][4];
        #pragma unroll
        for (int nt = 0; nt < 8; nt++) { sf[nt][0] = sf[nt][1] = sf[nt][2] = sf[nt][3] = 0.f; }
        #pragma unroll
        for (int ks = 0; ks < 12; ks++) {
            const int c = ks * 8 + (lane & 3);
            unsigned a[4];
            a[0] = Qs[r0loc * PQ + c];
            a[1] = Qs[(r0loc + 8) * PQ + c];
            a[2] = Qs[r0loc * PQ + c + 4];
            a[3] = Qs[(r0loc + 8) * PQ + c + 4];
            #pragma unroll
            for (int nt = 0; nt < 8; nt++) {
                unsigned bb[2];
                int key = nt * 8 + (lane >> 2);
                bb[0] = Ks[key * PK + c];
                bb[1] = Ks[key * PK + c + 4];
                mma_tf32(sf[nt], a, bb);
            }
        }

        float mt0 = -1e30f, mt1 = -1e30f;
        #pragma unroll
        for (int nt = 0; nt < 8; nt++) {
            mt0 = fmaxf(mt0, fmaxf(sf[nt][0], sf[nt][1]));
            mt1 = fmaxf(mt1, fmaxf(sf[nt][2], sf[nt][3]));
        }
        mt0 = fmaxf(mt0, __shfl_xor_sync(0xffffffffu, mt0, 1));
        mt0 = fmaxf(mt0, __shfl_xor_sync(0xffffffffu, mt0, 2));
        mt1 = fmaxf(mt1, __shfl_xor_sync(0xffffffffu, mt1, 1));
        mt1 = fmaxf(mt1, __shfl_xor_sync(0xffffffffu, mt1, 2));
        const float mn0 = fmaxf(m0, mt0), mn1 = fmaxf(m1, mt1);
        const float al0 = __expf(m0 - mn0), al1 = __expf(m1 - mn1);
        m0 = mn0; m1 = mn1;

        float ps0 = 0.f, ps1 = 0.f;
        #pragma unroll
        for (int nt = 0; nt < 8; nt++) {
            int cc = nt * 8 + 2 * (lane & 3);
            float p00 = __expf(sf[nt][0] - mn0);
            float p01 = __expf(sf[nt][1] - mn0);
            float p10 = __expf(sf[nt][2] - mn1);
            float p11 = __expf(sf[nt][3] - mn1);
            ps0 += p00 + p01;
            ps1 += p10 + p11;
            Ps[r0loc * PP + cc]           = f2tf(p00);
            Ps[r0loc * PP + cc + 1]       = f2tf(p01);
            Ps[(r0loc + 8) * PP + cc]     = f2tf(p10);
            Ps[(r0loc + 8) * PP + cc + 1] = f2tf(p11);
        }
        ps0 += __shfl_xor_sync(0xffffffffu, ps0, 1);
        ps0 += __shfl_xor_sync(0xffffffffu, ps0, 2);
        ps1 += __shfl_xor_sync(0xffffffffu, ps1, 1);
        ps1 += __shfl_xor_sync(0xffffffffu, ps1, 2);
        l0 = l0 * al0 + ps0;
        l1 = l1 * al1 + ps1;

        #pragma unroll
        for (int i = 0; i < 12; i++) {
            o[i][0] *= al0; o[i][1] *= al0;
            o[i][2] *= al1; o[i][3] *= al1;
        }
        __syncwarp();

        #pragma unroll
        for (int ks = 0; ks < 8; ks++) {
            const int kk = ks * 8 + (lane & 3);
            unsigned a[4];
            a[0] = Ps[r0loc * PP + kk];
            a[1] = Ps[(r0loc + 8) * PP + kk];
            a[2] = Ps[r0loc * PP + kk + 4];
            a[3] = Ps[(r0loc + 8) * PP + kk + 4];
            #pragma unroll
            for (int nt = 0; nt < 12; nt++) {
                unsigned bb[2];
                int n = nt * 8 + (lane >> 2);
                bb[0] = Vs[kk * PV + n];
                bb[1] = Vs[(kk + 4) * PV + n];
                mma_tf32(o[nt], a, bb);
            }
        }
    }

    const float inv0 = 1.f / l0, inv1 = 1.f / l1;
    #pragma unroll
    for (int nt = 0; nt < 12; nt++) {
        int cc = nt * 8 + 2 * (lane & 3);
        size_t base0 = (size_t)(b * Ln + r0loc) * HHD + h * HDn + cc;
        size_t base1 = (size_t)(b * Ln + r0loc + 8) * HHD + h * HDn + cc;
        Og[base0]     = o[nt][0] * inv0;
        Og[base0 + 1] = o[nt][1] * inv0;
        Og[base1]     = o[nt][2] * inv1;
        Og[base1 + 1] = o[nt][3] * inv1;
    }
}

// ---------------- host orchestration ----------------
extern "C" void kernel_launch(void* const* d_in, const int* in_sizes, int n_in,
                              void* d_out, int out_size)
{
    const float* context = (const float*)d_in[0];
    const float* latents = (const float*)d_in[1];
    const float* ctx_g   = (const float*)d_in[2];
    const float* ctx_b   = (const float*)d_in[3];
    const float* lat_g   = (const float*)d_in[4];
    const float* lat_b   = (const float*)d_in[5];
    const float* q_g     = (const float*)d_in[6];
    const float* q_b     = (const float*)d_in[7];
    const float* k_g     = (const float*)d_in[8];
    const float* k_b     = (const float*)d_in[9];
    const float* Wq      = (const float*)d_in[10];
    const float* Wk      = (const float*)d_in[11];
    const float* Wv      = (const float*)d_in[12];
    const float* Wo      = (const float*)d_in[13];
    const float* mlp_g   = (const float*)d_in[14];
    const float* mlp_b   = (const float*)d_in[15];
    const float* Wfc     = (const float*)d_in[16];
    const float* Wcp     = (const float*)d_in[17];
    const float* f_g     = (const float*)d_in[18];
    const float* f_b     = (const float*)d_in[19];
    float* out = (float*)d_out;

    float *xhat, *lat, *lhat, *mlph, *Kc0, *Vc0, *Qb, *Kl, *Vl, *att, *hid;
    cudaGetSymbolAddress((void**)&xhat, g_xhat);
    cudaGetSymbolAddress((void**)&lat,  g_lat);
    cudaGetSymbolAddress((void**)&lhat, g_lhat);
    cudaGetSymbolAddress((void**)&mlph, g_mlph);
    cudaGetSymbolAddress((void**)&Kc0,  g_Kc);
    cudaGetSymbolAddress((void**)&Vc0,  g_Vc);
    cudaGetSymbolAddress((void**)&Qb,   g_Q);
    cudaGetSymbolAddress((void**)&Kl,   g_Kl);
    cudaGetSymbolAddress((void**)&Vl,   g_Vl);
    cudaGetSymbolAddress((void**)&att,  g_att);
    cudaGetSymbolAddress((void**)&hid,  g_hid);
    const size_t KV_STRIDE = (size_t)Bn * Sn * HHD;

    cudaFuncSetAttribute(attn_kernel, cudaFuncAttributeMaxDynamicSharedMemorySize, ATTN_SMEM);

    static cudaStream_t s1 = nullptr;
    static cudaEvent_t ev0, evLat, evKV[DEPTHn], evAttn[DEPTHn];
    if (s1 == nullptr) {
        int prLo, prHi;
        cudaDeviceGetStreamPriorityRange(&prLo, &prHi);
        cudaStreamCreateWithPriority(&s1, cudaStreamNonBlocking, prHi);
        cudaEventCreateWithFlags(&ev0, cudaEventDisableTiming);
        cudaEventCreateWithFlags(&evLat, cudaEventDisableTiming);
        for (int i = 0; i < DEPTHn; i++) {
            cudaEventCreateWithFlags(&evKV[i], cudaEventDisableTiming);
            cudaEventCreateWithFlags(&evAttn[i], cudaEventDisableTiming);
        }
    }

    const int MBIG = Bn * Sn;   // 73728
    const int MLAT = Bn * Ln;   // 2048
    const int gridBig = (MBIG / BM) * (HHD / BN);       // 6912 (x2 in z for K+V)
    const int gridQKV = (MLAT / BM) * (HHD / BN);       // 192 (x3 in z)
    const int gridWo  = (MLAT / BM) * (Dn / BN);        // 160
    const int gridFc  = (MLAT / BM) * (INTERn / BN);    // 640

    cudaEventRecord(ev0, 0);
    cudaStreamWaitEvent(s1, ev0, 0);

    ln_kernel<false><<<MBIG, 256>>>(context, xhat, nullptr, nullptr);
    bcast_lat<<<(Bn * Ln * Dn + 255) / 256, 256, 0, s1>>>(latents, lat);

    for (int i = 0; i < DEPTHn; i++) {
        const int p = i & 1;
        float* Kc = Kc0 + p * KV_STRIDE;
        float* Vc = Vc0 + p * KV_STRIDE;
        const float* Wqi  = Wq  + (size_t)i * Dn * HHD;
        const float* Wki  = Wk  + (size_t)i * Dn * HHD;
        const float* Wvi  = Wv  + (size_t)i * Dn * HHD;
        const float* Woi  = Wo  + (size_t)i * HHD * Dn;
        const float* Wfci = Wfc + (size_t)i * Dn * INTERn;
        const float* Wcpi = Wcp + (size_t)i * INTERn * Dn;

        // ---- stream0: combined big context K+V GEMM ----
        if (i >= 2) cudaStreamWaitEvent(0, evAttn[i - 2], 0);
        gemm_kv<<<dim3(gridBig, 1, 2), 256>>>(xhat, Wki, Wvi, Kc, Vc, MBIG, HHD, Dn,
                                              ctx_g + i * Dn, ctx_b + i * Dn);
        cudaEventRecord(evKV[i], 0);

        // ---- stream1 (high priority): latent chain ----
        ln_kernel<true><<<MLAT, 256, 0, s1>>>(lat, lhat, lat_g + i * Dn, lat_b + i * Dn);
        gemm_qkv<<<dim3(gridQKV, 1, 3), 256, 0, s1>>>(lhat, Wqi, Wki, Wvi,
                                                      Qb, Kl, Vl, MLAT, HHD, Dn);
        cudaStreamWaitEvent(s1, evKV[i], 0);
        attn_kernel<<<Bn * Hn, 128, ATTN_SMEM, s1>>>(Qb, Kc, Kl, Vc, Vl, att,
                                                     q_g + i * HDn, q_b + i * HDn,
                                                     k_g + i * HDn, k_b + i * HDn);
        cudaEventRecord(evAttn[i], s1);
        gemm_tf32<0,2><<<gridWo, 256, 0, s1>>>(att, Woi, lat, MLAT, Dn, HHD,
                                               nullptr, nullptr, lat);
        ln_kernel<true><<<MLAT, 256, 0, s1>>>(lat, mlph, mlp_g + i * Dn, mlp_b + i * Dn);
        gemm_tf32<0,1><<<gridFc, 256, 0, s1>>>(mlph, Wfci, hid, MLAT, INTERn, Dn,
                                               nullptr, nullptr, nullptr);
        gemm_tf32<0,2><<<gridWo, 256, 0, s1>>>(hid, Wcpi, lat, MLAT, Dn, INTERn,
                                               nullptr, nullptr, lat);
    }

    cudaEventRecord(evLat, s1);
    cudaStreamWaitEvent(0, evLat, 0);
    ln_kernel<true><<<MLAT, 256>>>(lat, out, f_g, f_b);
}